// round 2
// baseline (speedup 1.0000x reference)
#include <cuda_runtime.h>
#include <math.h>

// Problem constants (fixed shapes from reference)
constexpr int B_ = 4, L_ = 2048, E_ = 512, H_ = 8, D_ = 512, FE_ = 2048; // FE = FW*E

#define FLAG_RELU  1
#define FLAG_ACCUM 2
#define FLAG_CMASK 4
#define FLAG_CK    8

// ---------------- static scratch (allocation-free) ----------------
__device__ float g_xn[(size_t)B_ * L_ * E_];              //  16.8 MB
__device__ float g_Qh[(size_t)B_ * H_ * L_ * D_];         // 134 MB (also reused for per-head attn output)
__device__ float g_Kh[(size_t)B_ * H_ * L_ * D_];         // 134 MB
__device__ float g_Vh[(size_t)B_ * H_ * L_ * D_];         // 134 MB
__device__ float g_S [(size_t)B_ * H_ * L_ * L_];         // 537 MB (also reused for FFN hidden)

// ---------------- block reductions (256 threads) ----------------
__device__ __forceinline__ float blk_sum(float v) {
    __shared__ float s[9];
    #pragma unroll
    for (int o = 16; o > 0; o >>= 1) v += __shfl_xor_sync(0xffffffffu, v, o);
    int w = threadIdx.x >> 5, lane = threadIdx.x & 31;
    __syncthreads();
    if (lane == 0) s[w] = v;
    __syncthreads();
    if (w == 0) {
        float t = (lane < 8) ? s[lane] : 0.0f;
        #pragma unroll
        for (int o = 4; o > 0; o >>= 1) t += __shfl_xor_sync(0xffffffffu, t, o);
        if (lane == 0) s[8] = t;
    }
    __syncthreads();
    return s[8];
}

__device__ __forceinline__ float blk_max(float v) {
    __shared__ float s[9];
    #pragma unroll
    for (int o = 16; o > 0; o >>= 1) v = fmaxf(v, __shfl_xor_sync(0xffffffffu, v, o));
    int w = threadIdx.x >> 5, lane = threadIdx.x & 31;
    __syncthreads();
    if (lane == 0) s[w] = v;
    __syncthreads();
    if (w == 0) {
        float t = (lane < 8) ? s[lane] : -3.4e38f;
        #pragma unroll
        for (int o = 4; o > 0; o >>= 1) t = fmaxf(t, __shfl_xor_sync(0xffffffffu, t, o));
        if (lane == 0) s[8] = t;
    }
    __syncthreads();
    return s[8];
}

// ---------------- LayerNorm: one block (256 thr) per row of E=512 ----------------
__global__ void ln_kernel(const float* __restrict__ x, const float* __restrict__ g,
                          const float* __restrict__ b, float* __restrict__ y) {
    long long row = blockIdx.x;
    const float* xr = x + row * E_;
    float*       yr = y + row * E_;
    int t = threadIdx.x;
    float a0 = xr[t], a1 = xr[t + 256];
    float mean = blk_sum(a0 + a1) * (1.0f / E_);
    float d0 = a0 - mean, d1 = a1 - mean;
    float var = blk_sum(d0 * d0 + d1 * d1) * (1.0f / E_);
    float inv = rsqrtf(var + 1e-5f);
    yr[t]       = d0 * inv * g[t]       + b[t];
    yr[t + 256] = d1 * inv * g[t + 256] + b[t + 256];
}

// ---------------- Softmax: one block (256 thr) per row of L=2048 ----------------
__global__ void softmax_kernel(float* __restrict__ S) {
    long long row = blockIdx.x;
    float* r = S + row * (long long)L_;
    int t = threadIdx.x;
    float v[8];
    float mx = -3.4e38f;
    #pragma unroll
    for (int i = 0; i < 8; i++) { v[i] = r[t + i * 256]; mx = fmaxf(mx, v[i]); }
    mx = blk_max(mx);
    float s = 0.0f;
    #pragma unroll
    for (int i = 0; i < 8; i++) { v[i] = __expf(v[i] - mx); s += v[i]; }
    s = blk_sum(s);
    float inv = 1.0f / s;
    #pragma unroll
    for (int i = 0; i < 8; i++) r[t + i * 256] = v[i] * inv;
}

// ---------------- out[idx] = base[idx] + mean_h Oh[b,h,l,e] ----------------
__global__ void add_mean_kernel(const float* __restrict__ base, const float* __restrict__ Oh,
                                float* __restrict__ out) {
    long long idx = (long long)blockIdx.x * 256 + threadIdx.x;       // over B*L*E
    long long b   = idx >> 20;                                       // L*E = 2^20
    long long rem = idx & ((1LL << 20) - 1);
    const float* p = Oh + b * ((long long)H_ * L_ * D_) + rem;
    float s = 0.0f;
    #pragma unroll
    for (int h = 0; h < H_; h++) s += p[(long long)h * L_ * D_];
    out[idx] = base[idx] + s * (1.0f / H_);
}

// ---------------- Tiled GEMM: C[z] = alpha * A[z] * op(B[z]) (+bias)(relu)(+C)(causal) ----
// BM=BN=128, BK=8, 256 threads, 8x8 per thread. All dims assumed divisible.
template <bool TRANSB>
__global__ __launch_bounds__(256) void gemm128(
    const float* __restrict__ A, const float* __restrict__ Bm, float* __restrict__ C,
    int M, int N, int K,
    int divA, long long sA, int modB, long long sB, long long sC,
    const float* __restrict__ bias, float alpha, int flags)
{
    constexpr int BM = 128, BN = 128, BK = 8;
    int z = blockIdx.z;
    A  += (long long)(z / divA) * sA;
    Bm += (long long)(z % modB) * sB;
    C  += (long long)z * sC;

    const int row0 = blockIdx.y * BM;
    const int col0 = blockIdx.x * BN;

    // Fully-masked causal block: skip compute entirely.
    if ((flags & FLAG_CMASK) && col0 > row0 + BM - 1) {
        for (int i = threadIdx.x; i < BM * BN; i += 256) {
            int r = i >> 7, c = i & 127;
            C[(long long)(row0 + r) * N + (col0 + c)] = -1e30f;
        }
        return;
    }

    __shared__ __align__(16) float As[BK][BM];
    __shared__ __align__(16) float Bs[BK][BN];

    const int tid = threadIdx.x;
    const int tx = tid & 15, ty = tid >> 4;

    float acc[8][8];
    #pragma unroll
    for (int i = 0; i < 8; i++)
        #pragma unroll
        for (int j = 0; j < 8; j++) acc[i][j] = 0.0f;

    const int arow = tid >> 1, ac4 = (tid & 1) * 4;   // A (and NT-B) load mapping
    const int brow = tid >> 5, bc4 = (tid & 31) * 4;  // NN-B load mapping

    int Kend = K;
    if (flags & FLAG_CK) Kend = min(K, row0 + BM);    // S rows beyond diag are exact 0

    for (int k0 = 0; k0 < Kend; k0 += BK) {
        float4 av = *(const float4*)(A + (long long)(row0 + arow) * K + k0 + ac4);
        As[ac4 + 0][arow] = av.x; As[ac4 + 1][arow] = av.y;
        As[ac4 + 2][arow] = av.z; As[ac4 + 3][arow] = av.w;
        if (TRANSB) {
            float4 bv = *(const float4*)(Bm + (long long)(col0 + arow) * K + k0 + ac4);
            Bs[ac4 + 0][arow] = bv.x; Bs[ac4 + 1][arow] = bv.y;
            Bs[ac4 + 2][arow] = bv.z; Bs[ac4 + 3][arow] = bv.w;
        } else {
            float4 bv = *(const float4*)(Bm + (long long)(k0 + brow) * N + col0 + bc4);
            *(float4*)&Bs[brow][bc4] = bv;
        }
        __syncthreads();
        #pragma unroll
        for (int kk = 0; kk < BK; kk++) {
            float4 a0 = *(const float4*)&As[kk][ty * 8];
            float4 a1 = *(const float4*)&As[kk][ty * 8 + 4];
            float4 b0 = *(const float4*)&Bs[kk][tx * 4];
            float4 b1 = *(const float4*)&Bs[kk][64 + tx * 4];
            float a[8] = {a0.x, a0.y, a0.z, a0.w, a1.x, a1.y, a1.z, a1.w};
            float b[8] = {b0.x, b0.y, b0.z, b0.w, b1.x, b1.y, b1.z, b1.w};
            #pragma unroll
            for (int i = 0; i < 8; i++)
                #pragma unroll
                for (int j = 0; j < 8; j++) acc[i][j] += a[i] * b[j];
        }
        __syncthreads();
    }

    // epilogue (columns split: tx*4..+3 and 64+tx*4..+3)
    #pragma unroll
    for (int i = 0; i < 8; i++) {
        int r = row0 + ty * 8 + i;
        #pragma unroll
        for (int j = 0; j < 8; j++) {
            int c = col0 + ((j < 4) ? (tx * 4 + j) : (64 + tx * 4 + j - 4));
            float v = acc[i][j] * alpha;
            if (bias) v += bias[c];
            if (flags & FLAG_RELU) v = fmaxf(v, 0.0f);
            if ((flags & FLAG_CMASK) && c > r) v = -1e30f;
            long long o = (long long)r * N + c;
            if (flags & FLAG_ACCUM) C[o] += v;
            else                    C[o] = v;
        }
    }
}

// ---------------- host orchestration ----------------
extern "C" void kernel_launch(void* const* d_in, const int* in_sizes, int n_in,
                              void* d_out, int out_size) {
    const float* q    = (const float*)d_in[0];
    const float* k    = (const float*)d_in[1];
    const float* v    = (const float*)d_in[2];
    const float* Wq_s = (const float*)d_in[3];
    const float* Wk_s = (const float*)d_in[4];
    const float* Wv_s = (const float*)d_in[5];
    const float* Wq_c = (const float*)d_in[6];
    const float* Wk_c = (const float*)d_in[7];
    const float* Wv_c = (const float*)d_in[8];
    const float* W1   = (const float*)d_in[9];
    const float* b1   = (const float*)d_in[10];
    const float* W2   = (const float*)d_in[11];
    const float* b2   = (const float*)d_in[12];
    const float* g1   = (const float*)d_in[13];
    const float* be1  = (const float*)d_in[14];
    const float* g2   = (const float*)d_in[15];
    const float* be2  = (const float*)d_in[16];
    const float* g3   = (const float*)d_in[17];
    const float* be3  = (const float*)d_in[18];
    float* out = (float*)d_out;

    float *xn, *Qh, *Kh, *Vh, *S;
    cudaGetSymbolAddress((void**)&xn, g_xn);
    cudaGetSymbolAddress((void**)&Qh, g_Qh);
    cudaGetSymbolAddress((void**)&Kh, g_Kh);
    cudaGetSymbolAddress((void**)&Vh, g_Vh);
    cudaGetSymbolAddress((void**)&S,  g_S);

    const long long sLE = (long long)L_ * E_;  // per-batch activation stride
    const long long sED = (long long)E_ * D_;  // per-head weight stride
    const long long sLD = (long long)L_ * D_;  // per (b,h) Q/K/V stride
    const long long sLL = (long long)L_ * L_;  // per (b,h) score stride
    const int BIG = 1 << 30;
    const float scl = 0.044194173824159216f;   // 512^-0.5

    const dim3 gProj(D_ / 128, L_ / 128, B_ * H_);   // (4,16,32)
    const dim3 gScore(L_ / 128, L_ / 128, B_ * H_);  // (16,16,32)

    // ===== Block 1: pre-norm causal self-attention =====
    ln_kernel<<<B_ * L_, 256>>>(q, g1, be1, xn);
    gemm128<false><<<gProj, 256>>>(xn, Wq_s, Qh, L_, D_, E_, H_, sLE, H_, sED, sLD, nullptr, 1.f, 0);
    gemm128<false><<<gProj, 256>>>(xn, Wk_s, Kh, L_, D_, E_, H_, sLE, H_, sED, sLD, nullptr, 1.f, 0);
    gemm128<false><<<gProj, 256>>>(xn, Wv_s, Vh, L_, D_, E_, H_, sLE, H_, sED, sLD, nullptr, 1.f, 0);
    gemm128<true ><<<gScore, 256>>>(Qh, Kh, S, L_, L_, D_, 1, sLD, BIG, sLD, sLL, nullptr, scl, FLAG_CMASK);
    softmax_kernel<<<B_ * H_ * L_, 256>>>(S);
    gemm128<false><<<gProj, 256>>>(S, Vh, Qh, L_, D_, L_, 1, sLL, BIG, sLD, sLD, nullptr, 1.f, FLAG_CK);
    add_mean_kernel<<<(B_ * L_ * E_) / 256, 256>>>(q, Qh, out);   // out = q + mean_h(O)

    // ===== Block 2: pre-norm cross-attention (only queries normed) =====
    ln_kernel<<<B_ * L_, 256>>>(out, g2, be2, xn);
    gemm128<false><<<gProj, 256>>>(xn, Wq_c, Qh, L_, D_, E_, H_, sLE, H_, sED, sLD, nullptr, 1.f, 0);
    gemm128<false><<<gProj, 256>>>(k,  Wk_c, Kh, L_, D_, E_, H_, sLE, H_, sED, sLD, nullptr, 1.f, 0);
    gemm128<false><<<gProj, 256>>>(v,  Wv_c, Vh, L_, D_, E_, H_, sLE, H_, sED, sLD, nullptr, 1.f, 0);
    gemm128<true ><<<gScore, 256>>>(Qh, Kh, S, L_, L_, D_, 1, sLD, BIG, sLD, sLL, nullptr, scl, 0);
    softmax_kernel<<<B_ * H_ * L_, 256>>>(S);
    gemm128<false><<<gProj, 256>>>(S, Vh, Qh, L_, D_, L_, 1, sLL, BIG, sLD, sLD, nullptr, 1.f, 0);
    add_mean_kernel<<<(B_ * L_ * E_) / 256, 256>>>(out, Qh, out); // out += mean_h(O)

    // ===== Block 3: FFN =====
    ln_kernel<<<B_ * L_, 256>>>(out, g3, be3, xn);
    // hidden = relu(xn @ W1 + b1), stored in S scratch: [B*L, 4E]
    gemm128<false><<<dim3(FE_ / 128, (B_ * L_) / 128, 1), 256>>>(
        xn, W1, S, B_ * L_, FE_, E_, 1, 0, BIG, 0, 0, b1, 1.f, FLAG_RELU);
    // out += hidden @ W2 + b2
    gemm128<false><<<dim3(E_ / 128, (B_ * L_) / 128, 1), 256>>>(
        S, W2, out, B_ * L_, E_, FE_, 1, 0, BIG, 0, 0, b2, 1.f, FLAG_ACCUM);
}

// round 3
// speedup vs baseline: 1.3636x; 1.3636x over previous
#include <cuda_runtime.h>
#include <math.h>
#include <stdint.h>

// Problem constants (fixed shapes from reference)
constexpr int B_ = 4, L_ = 2048, E_ = 512, H_ = 8, D_ = 512, FE_ = 2048; // FE = FW*E

#define FLAG_RELU  1
#define FLAG_ACCUM 2
#define FLAG_CMASK 4
#define FLAG_CK    8

// ---------------- static scratch (allocation-free) ----------------
__device__ float g_xn[(size_t)B_ * L_ * E_];              //  16.8 MB
__device__ float g_Qh[(size_t)B_ * H_ * L_ * D_];         // 134 MB (also reused for per-head attn output)
__device__ float g_Kh[(size_t)B_ * H_ * L_ * D_];         // 134 MB
__device__ float g_Vh[(size_t)B_ * H_ * L_ * D_];         // 134 MB
__device__ float g_S [(size_t)B_ * H_ * L_ * L_];         // 537 MB (also reused for FFN hidden)

// ---------------- block reductions (256 threads) ----------------
__device__ __forceinline__ float blk_sum(float v) {
    __shared__ float s[9];
    #pragma unroll
    for (int o = 16; o > 0; o >>= 1) v += __shfl_xor_sync(0xffffffffu, v, o);
    int w = threadIdx.x >> 5, lane = threadIdx.x & 31;
    __syncthreads();
    if (lane == 0) s[w] = v;
    __syncthreads();
    if (w == 0) {
        float t = (lane < 8) ? s[lane] : 0.0f;
        #pragma unroll
        for (int o = 4; o > 0; o >>= 1) t += __shfl_xor_sync(0xffffffffu, t, o);
        if (lane == 0) s[8] = t;
    }
    __syncthreads();
    return s[8];
}

__device__ __forceinline__ float blk_max(float v) {
    __shared__ float s[9];
    #pragma unroll
    for (int o = 16; o > 0; o >>= 1) v = fmaxf(v, __shfl_xor_sync(0xffffffffu, v, o));
    int w = threadIdx.x >> 5, lane = threadIdx.x & 31;
    __syncthreads();
    if (lane == 0) s[w] = v;
    __syncthreads();
    if (w == 0) {
        float t = (lane < 8) ? s[lane] : -3.4e38f;
        #pragma unroll
        for (int o = 4; o > 0; o >>= 1) t = fmaxf(t, __shfl_xor_sync(0xffffffffu, t, o));
        if (lane == 0) s[8] = t;
    }
    __syncthreads();
    return s[8];
}

// ---------------- LayerNorm: one block (256 thr) per row of E=512 ----------------
__global__ void ln_kernel(const float* __restrict__ x, const float* __restrict__ g,
                          const float* __restrict__ b, float* __restrict__ y) {
    long long row = blockIdx.x;
    const float* xr = x + row * E_;
    float*       yr = y + row * E_;
    int t = threadIdx.x;
    float a0 = xr[t], a1 = xr[t + 256];
    float mean = blk_sum(a0 + a1) * (1.0f / E_);
    float d0 = a0 - mean, d1 = a1 - mean;
    float var = blk_sum(d0 * d0 + d1 * d1) * (1.0f / E_);
    float inv = rsqrtf(var + 1e-5f);
    yr[t]       = d0 * inv * g[t]       + b[t];
    yr[t + 256] = d1 * inv * g[t + 256] + b[t + 256];
}

// ---------------- Softmax: one block (256 thr) per row of L=2048 ----------------
__global__ void softmax_kernel(float* __restrict__ S) {
    long long row = blockIdx.x;
    float* r = S + row * (long long)L_;
    int t = threadIdx.x;
    float v[8];
    float mx = -3.4e38f;
    #pragma unroll
    for (int i = 0; i < 8; i++) { v[i] = r[t + i * 256]; mx = fmaxf(mx, v[i]); }
    mx = blk_max(mx);
    float s = 0.0f;
    #pragma unroll
    for (int i = 0; i < 8; i++) { v[i] = __expf(v[i] - mx); s += v[i]; }
    s = blk_sum(s);
    float inv = 1.0f / s;
    #pragma unroll
    for (int i = 0; i < 8; i++) r[t + i * 256] = v[i] * inv;
}

// ---------------- out[idx] = base[idx] + mean_h Oh[b,h,l,e] ----------------
__global__ void add_mean_kernel(const float* __restrict__ base, const float* __restrict__ Oh,
                                float* __restrict__ out) {
    long long idx = (long long)blockIdx.x * 256 + threadIdx.x;       // over B*L*E
    long long b   = idx >> 20;                                       // L*E = 2^20
    long long rem = idx & ((1LL << 20) - 1);
    const float* p = Oh + b * ((long long)H_ * L_ * D_) + rem;
    float s = 0.0f;
    #pragma unroll
    for (int h = 0; h < H_; h++) s += p[(long long)h * L_ * D_];
    out[idx] = base[idx] + s * (1.0f / H_);
}

// ---------------- tf32 helpers ----------------
__device__ __forceinline__ uint32_t f2tf32(float x) {
    uint32_t r;
    asm("cvt.rna.tf32.f32 %0, %1;" : "=r"(r) : "f"(x));
    return r;
}

__device__ __forceinline__ void mma_tf32(float d[4], const uint32_t a[4], const uint32_t b[2]) {
    asm volatile(
        "mma.sync.aligned.m16n8k8.row.col.f32.tf32.tf32.f32 "
        "{%0,%1,%2,%3}, {%4,%5,%6,%7}, {%8,%9}, {%0,%1,%2,%3};"
        : "+f"(d[0]), "+f"(d[1]), "+f"(d[2]), "+f"(d[3])
        : "r"(a[0]), "r"(a[1]), "r"(a[2]), "r"(a[3]), "r"(b[0]), "r"(b[1]));
}

// ---------------- Tensor-core GEMM: C[z] = alpha * A[z] * op(B[z]) (+bias)(relu)(+C)(causal)
// BM=BN=128, BK=32, 256 threads = 8 warps (4x2), warp tile 32x64, mma m16n8k8 tf32.
template <bool TRANSB>
__global__ __launch_bounds__(256) void gemm_tc(
    const float* __restrict__ A, const float* __restrict__ Bm, float* __restrict__ C,
    int M, int N, int K,
    int divA, long long sA, int modB, long long sB, long long sC,
    const float* __restrict__ bias, float alpha, int flags)
{
    constexpr int BM = 128, BN = 128, BK = 32;
    int z = blockIdx.z;
    A  += (long long)(z / divA) * sA;
    Bm += (long long)(z % modB) * sB;
    C  += (long long)z * sC;

    const int row0 = blockIdx.y * BM;
    const int col0 = blockIdx.x * BN;

    // Fully-masked causal block: skip compute entirely.
    if ((flags & FLAG_CMASK) && col0 > row0 + BM - 1) {
        for (int i = threadIdx.x; i < BM * BN; i += 256) {
            int r = i >> 7, c = i & 127;
            C[(long long)(row0 + r) * N + (col0 + c)] = -1e30f;
        }
        return;
    }

    // As: [128][33] (row-major, padded). Bs: NT [128][33] / NN [32][129]. 4224 words covers both.
    __shared__ uint32_t As[128 * 33];
    __shared__ uint32_t Bs[128 * 33];

    const int tid  = threadIdx.x;
    const int lane = tid & 31, wid = tid >> 5;
    const int wm = wid & 3, wn = wid >> 2;          // warp at (wm*32, wn*64)
    const int g = lane >> 2, tig = lane & 3;        // mma groupID / thread-in-group

    float acc[16][4];
    #pragma unroll
    for (int i = 0; i < 16; i++)
        #pragma unroll
        for (int j = 0; j < 4; j++) acc[i][j] = 0.0f;

    int Kend = K;
    if (flags & FLAG_CK) Kend = min(K, row0 + BM);   // S rows beyond diag are exact 0

    for (int k0 = 0; k0 < Kend; k0 += BK) {
        // --- stage A tile [128 x 32] (convert to tf32 on store) ---
        #pragma unroll
        for (int i = 0; i < 4; i++) {
            int s = tid + i * 256;                   // 1024 float4 slots
            int row = s >> 3, c4 = (s & 7) * 4;
            float4 v = *(const float4*)(A + (long long)(row0 + row) * K + k0 + c4);
            uint32_t* p = &As[row * 33 + c4];
            p[0] = f2tf32(v.x); p[1] = f2tf32(v.y); p[2] = f2tf32(v.z); p[3] = f2tf32(v.w);
        }
        // --- stage B tile ---
        if (TRANSB) {       // B is [N, K] row-major -> Bs[n][k]
            #pragma unroll
            for (int i = 0; i < 4; i++) {
                int s = tid + i * 256;
                int row = s >> 3, c4 = (s & 7) * 4;
                float4 v = *(const float4*)(Bm + (long long)(col0 + row) * K + k0 + c4);
                uint32_t* p = &Bs[row * 33 + c4];
                p[0] = f2tf32(v.x); p[1] = f2tf32(v.y); p[2] = f2tf32(v.z); p[3] = f2tf32(v.w);
            }
        } else {            // B is [K, N] row-major -> Bs[k][n]
            #pragma unroll
            for (int i = 0; i < 4; i++) {
                int s = tid + i * 256;
                int row = s >> 5, c4 = (s & 31) * 4;
                float4 v = *(const float4*)(Bm + (long long)(k0 + row) * N + col0 + c4);
                uint32_t* p = &Bs[row * 129 + c4];
                p[0] = f2tf32(v.x); p[1] = f2tf32(v.y); p[2] = f2tf32(v.z); p[3] = f2tf32(v.w);
            }
        }
        __syncthreads();

        #pragma unroll
        for (int kk = 0; kk < BK; kk += 8) {
            uint32_t afr[2][4];
            #pragma unroll
            for (int mt = 0; mt < 2; mt++) {
                int rA = wm * 32 + mt * 16;
                afr[mt][0] = As[(rA + g)     * 33 + kk + tig];
                afr[mt][1] = As[(rA + g + 8) * 33 + kk + tig];
                afr[mt][2] = As[(rA + g)     * 33 + kk + tig + 4];
                afr[mt][3] = As[(rA + g + 8) * 33 + kk + tig + 4];
            }
            uint32_t bfr[8][2];
            #pragma unroll
            for (int nt = 0; nt < 8; nt++) {
                int nb = wn * 64 + nt * 8;
                if (TRANSB) {
                    bfr[nt][0] = Bs[(nb + g) * 33 + kk + tig];
                    bfr[nt][1] = Bs[(nb + g) * 33 + kk + tig + 4];
                } else {
                    bfr[nt][0] = Bs[(kk + tig)     * 129 + nb + g];
                    bfr[nt][1] = Bs[(kk + tig + 4) * 129 + nb + g];
                }
            }
            #pragma unroll
            for (int mt = 0; mt < 2; mt++)
                #pragma unroll
                for (int nt = 0; nt < 8; nt++)
                    mma_tf32(acc[mt * 8 + nt], afr[mt], bfr[nt]);
        }
        __syncthreads();
    }

    // ---------------- epilogue ----------------
    #pragma unroll
    for (int mt = 0; mt < 2; mt++) {
        #pragma unroll
        for (int nt = 0; nt < 8; nt++) {
            float* a4 = acc[mt * 8 + nt];
            int rb = row0 + wm * 32 + mt * 16 + g;
            int cb = col0 + wn * 64 + nt * 8 + tig * 2;
            #pragma unroll
            for (int j = 0; j < 4; j++) {
                int r = rb + (j >> 1) * 8;          // j=0,1 -> rb ; j=2,3 -> rb+8
                int c = cb + (j & 1);
                float v = a4[j] * alpha;
                if (bias) v += bias[c];
                if (flags & FLAG_RELU) v = fmaxf(v, 0.0f);
                if ((flags & FLAG_CMASK) && c > r) v = -1e30f;
                long long o = (long long)r * N + c;
                if (flags & FLAG_ACCUM) C[o] += v;
                else                    C[o] = v;
            }
        }
    }
}

// ---------------- host orchestration ----------------
extern "C" void kernel_launch(void* const* d_in, const int* in_sizes, int n_in,
                              void* d_out, int out_size) {
    const float* q    = (const float*)d_in[0];
    const float* k    = (const float*)d_in[1];
    const float* v    = (const float*)d_in[2];
    const float* Wq_s = (const float*)d_in[3];
    const float* Wk_s = (const float*)d_in[4];
    const float* Wv_s = (const float*)d_in[5];
    const float* Wq_c = (const float*)d_in[6];
    const float* Wk_c = (const float*)d_in[7];
    const float* Wv_c = (const float*)d_in[8];
    const float* W1   = (const float*)d_in[9];
    const float* b1   = (const float*)d_in[10];
    const float* W2   = (const float*)d_in[11];
    const float* b2   = (const float*)d_in[12];
    const float* g1   = (const float*)d_in[13];
    const float* be1  = (const float*)d_in[14];
    const float* g2   = (const float*)d_in[15];
    const float* be2  = (const float*)d_in[16];
    const float* g3   = (const float*)d_in[17];
    const float* be3  = (const float*)d_in[18];
    float* out = (float*)d_out;

    float *xn, *Qh, *Kh, *Vh, *S;
    cudaGetSymbolAddress((void**)&xn, g_xn);
    cudaGetSymbolAddress((void**)&Qh, g_Qh);
    cudaGetSymbolAddress((void**)&Kh, g_Kh);
    cudaGetSymbolAddress((void**)&Vh, g_Vh);
    cudaGetSymbolAddress((void**)&S,  g_S);

    const long long sLE = (long long)L_ * E_;  // per-batch activation stride
    const long long sED = (long long)E_ * D_;  // per-head weight stride
    const long long sLD = (long long)L_ * D_;  // per (b,h) Q/K/V stride
    const long long sLL = (long long)L_ * L_;  // per (b,h) score stride
    const int BIG = 1 << 30;
    const float scl = 0.044194173824159216f;   // 512^-0.5

    const dim3 gProj(D_ / 128, L_ / 128, B_ * H_);   // (4,16,32)
    const dim3 gScore(L_ / 128, L_ / 128, B_ * H_);  // (16,16,32)

    // ===== Block 1: pre-norm causal self-attention =====
    ln_kernel<<<B_ * L_, 256>>>(q, g1, be1, xn);
    gemm_tc<false><<<gProj, 256>>>(xn, Wq_s, Qh, L_, D_, E_, H_, sLE, H_, sED, sLD, nullptr, 1.f, 0);
    gemm_tc<false><<<gProj, 256>>>(xn, Wk_s, Kh, L_, D_, E_, H_, sLE, H_, sED, sLD, nullptr, 1.f, 0);
    gemm_tc<false><<<gProj, 256>>>(xn, Wv_s, Vh, L_, D_, E_, H_, sLE, H_, sED, sLD, nullptr, 1.f, 0);
    gemm_tc<true ><<<gScore, 256>>>(Qh, Kh, S, L_, L_, D_, 1, sLD, BIG, sLD, sLL, nullptr, scl, FLAG_CMASK);
    softmax_kernel<<<B_ * H_ * L_, 256>>>(S);
    gemm_tc<false><<<gProj, 256>>>(S, Vh, Qh, L_, D_, L_, 1, sLL, BIG, sLD, sLD, nullptr, 1.f, FLAG_CK);
    add_mean_kernel<<<(B_ * L_ * E_) / 256, 256>>>(q, Qh, out);   // out = q + mean_h(O)

    // ===== Block 2: pre-norm cross-attention (only queries normed) =====
    ln_kernel<<<B_ * L_, 256>>>(out, g2, be2, xn);
    gemm_tc<false><<<gProj, 256>>>(xn, Wq_c, Qh, L_, D_, E_, H_, sLE, H_, sED, sLD, nullptr, 1.f, 0);
    gemm_tc<false><<<gProj, 256>>>(k,  Wk_c, Kh, L_, D_, E_, H_, sLE, H_, sED, sLD, nullptr, 1.f, 0);
    gemm_tc<false><<<gProj, 256>>>(v,  Wv_c, Vh, L_, D_, E_, H_, sLE, H_, sED, sLD, nullptr, 1.f, 0);
    gemm_tc<true ><<<gScore, 256>>>(Qh, Kh, S, L_, L_, D_, 1, sLD, BIG, sLD, sLL, nullptr, scl, 0);
    softmax_kernel<<<B_ * H_ * L_, 256>>>(S);
    gemm_tc<false><<<gProj, 256>>>(S, Vh, Qh, L_, D_, L_, 1, sLL, BIG, sLD, sLD, nullptr, 1.f, 0);
    add_mean_kernel<<<(B_ * L_ * E_) / 256, 256>>>(out, Qh, out); // out += mean_h(O)

    // ===== Block 3: FFN =====
    ln_kernel<<<B_ * L_, 256>>>(out, g3, be3, xn);
    // hidden = relu(xn @ W1 + b1), stored in S scratch: [B*L, 4E]
    gemm_tc<false><<<dim3(FE_ / 128, (B_ * L_) / 128, 1), 256>>>(
        xn, W1, S, B_ * L_, FE_, E_, 1, 0, BIG, 0, 0, b1, 1.f, FLAG_RELU);
    // out += hidden @ W2 + b2
    gemm_tc<false><<<dim3(E_ / 128, (B_ * L_) / 128, 1), 256>>>(
        S, W2, out, B_ * L_, E_, FE_, 1, 0, BIG, 0, 0, b2, 1.f, FLAG_ACCUM);
}

// round 4
// speedup vs baseline: 2.1560x; 1.5811x over previous
#include <cuda_runtime.h>
#include <math.h>
#include <stdint.h>

// Problem constants (fixed shapes from reference)
constexpr int B_ = 4, L_ = 2048, E_ = 512, H_ = 8, D_ = 512, FE_ = 2048; // FE = FW*E

#define FLAG_RELU  1
#define FLAG_ACCUM 2
#define FLAG_CMASK 4
#define FLAG_CK    8

// ---------------- static scratch (allocation-free) ----------------
__device__ float g_xn[(size_t)B_ * L_ * E_];              //  16.8 MB
__device__ float g_Qh[(size_t)B_ * H_ * L_ * D_];         // 134 MB (also per-head attn output)
__device__ float g_Kh[(size_t)B_ * H_ * L_ * D_];         // 134 MB
__device__ float g_Vh[(size_t)B_ * H_ * L_ * D_];         // 134 MB (stores V^T per head: [D][L])
__device__ float g_S [(size_t)B_ * H_ * L_ * L_];         // 537 MB (also FFN hidden)
__device__ float g_Wt[(size_t)3 * H_ * E_ * D_];          //  25 MB transposed weights

// ---------------- block reductions (256 threads) ----------------
__device__ __forceinline__ float blk_sum(float v) {
    __shared__ float s[9];
    #pragma unroll
    for (int o = 16; o > 0; o >>= 1) v += __shfl_xor_sync(0xffffffffu, v, o);
    int w = threadIdx.x >> 5, lane = threadIdx.x & 31;
    __syncthreads();
    if (lane == 0) s[w] = v;
    __syncthreads();
    if (w == 0) {
        float t = (lane < 8) ? s[lane] : 0.0f;
        #pragma unroll
        for (int o = 4; o > 0; o >>= 1) t += __shfl_xor_sync(0xffffffffu, t, o);
        if (lane == 0) s[8] = t;
    }
    __syncthreads();
    return s[8];
}

__device__ __forceinline__ float blk_max(float v) {
    __shared__ float s[9];
    #pragma unroll
    for (int o = 16; o > 0; o >>= 1) v = fmaxf(v, __shfl_xor_sync(0xffffffffu, v, o));
    int w = threadIdx.x >> 5, lane = threadIdx.x & 31;
    __syncthreads();
    if (lane == 0) s[w] = v;
    __syncthreads();
    if (w == 0) {
        float t = (lane < 8) ? s[lane] : -3.4e38f;
        #pragma unroll
        for (int o = 4; o > 0; o >>= 1) t = fmaxf(t, __shfl_xor_sync(0xffffffffu, t, o));
        if (lane == 0) s[8] = t;
    }
    __syncthreads();
    return s[8];
}

// ---------------- LayerNorm ----------------
__global__ void ln_kernel(const float* __restrict__ x, const float* __restrict__ g,
                          const float* __restrict__ b, float* __restrict__ y) {
    long long row = blockIdx.x;
    const float* xr = x + row * E_;
    float*       yr = y + row * E_;
    int t = threadIdx.x;
    float a0 = xr[t], a1 = xr[t + 256];
    float mean = blk_sum(a0 + a1) * (1.0f / E_);
    float d0 = a0 - mean, d1 = a1 - mean;
    float var = blk_sum(d0 * d0 + d1 * d1) * (1.0f / E_);
    float inv = rsqrtf(var + 1e-5f);
    yr[t]       = d0 * inv * g[t]       + b[t];
    yr[t + 256] = d1 * inv * g[t + 256] + b[t + 256];
}

// ---------------- Softmax ----------------
__global__ void softmax_kernel(float* __restrict__ S) {
    long long row = blockIdx.x;
    float* r = S + row * (long long)L_;
    int t = threadIdx.x;
    float v[8];
    float mx = -3.4e38f;
    #pragma unroll
    for (int i = 0; i < 8; i++) { v[i] = r[t + i * 256]; mx = fmaxf(mx, v[i]); }
    mx = blk_max(mx);
    float s = 0.0f;
    #pragma unroll
    for (int i = 0; i < 8; i++) { v[i] = __expf(v[i] - mx); s += v[i]; }
    s = blk_sum(s);
    float inv = 1.0f / s;
    #pragma unroll
    for (int i = 0; i < 8; i++) r[t + i * 256] = v[i] * inv;
}

// ---------------- out[idx] = base[idx] + mean_h Oh[b,h,l,e] ----------------
__global__ void add_mean_kernel(const float* __restrict__ base, const float* __restrict__ Oh,
                                float* __restrict__ out) {
    long long idx = (long long)blockIdx.x * 256 + threadIdx.x;       // over B*L*E
    long long b   = idx >> 20;                                       // L*E = 2^20
    long long rem = idx & ((1LL << 20) - 1);
    const float* p = Oh + b * ((long long)H_ * L_ * D_) + rem;
    float s = 0.0f;
    #pragma unroll
    for (int h = 0; h < H_; h++) s += p[(long long)h * L_ * D_];
    out[idx] = base[idx] + s * (1.0f / H_);
}

// ---------------- Batched transpose: Y[z][c][r] = X[z][r][c], 32x32 smem tiles ----
__global__ void transpose_kernel(const float* __restrict__ X, float* __restrict__ Y,
                                 int R, int Cc) {
    __shared__ float t[32][33];
    long long zo = (long long)blockIdx.z * R * Cc;
    int c0 = blockIdx.x * 32, r0 = blockIdx.y * 32;
    int tx = threadIdx.x & 31, ty = threadIdx.x >> 5;   // 256 threads, ty=0..7
    #pragma unroll
    for (int i = 0; i < 32; i += 8)
        t[ty + i][tx] = X[zo + (long long)(r0 + ty + i) * Cc + c0 + tx];
    __syncthreads();
    #pragma unroll
    for (int i = 0; i < 32; i += 8)
        Y[zo + (long long)(c0 + ty + i) * R + r0 + tx] = t[tx][ty + i];
}

// ---------------- tf32 / mma / ldmatrix helpers ----------------
__device__ __forceinline__ uint32_t f2tf32(float x) {
    uint32_t r;
    asm("cvt.rna.tf32.f32 %0, %1;" : "=r"(r) : "f"(x));
    return r;
}

__device__ __forceinline__ void mma_tf32(float d[4], const uint32_t a[4], const uint32_t b[2]) {
    asm volatile(
        "mma.sync.aligned.m16n8k8.row.col.f32.tf32.tf32.f32 "
        "{%0,%1,%2,%3}, {%4,%5,%6,%7}, {%8,%9}, {%0,%1,%2,%3};"
        : "+f"(d[0]), "+f"(d[1]), "+f"(d[2]), "+f"(d[3])
        : "r"(a[0]), "r"(a[1]), "r"(a[2]), "r"(a[3]), "r"(b[0]), "r"(b[1]));
}

__device__ __forceinline__ void ldsm4(uint32_t r[4], uint32_t addr) {
    asm volatile("ldmatrix.sync.aligned.m8n8.x4.shared.b16 {%0,%1,%2,%3}, [%4];"
                 : "=r"(r[0]), "=r"(r[1]), "=r"(r[2]), "=r"(r[3]) : "r"(addr));
}

// ---------------- Tensor-core GEMM (all-TRANSB): C[z] = alpha * A[z] * B[z]^T ...
// A: [M][K] row-major, B: [N][K] row-major. BM=BN=128, BK=32.
// 256 threads = 8 warps (4x2), warp tile 32x64, mma m16n8k8 tf32, ldmatrix fragments.
// SMEM layout: tile[row][k] at word row*32 + ((grp ^ (row&7))<<2) + (k&3), grp=k>>2.
__global__ __launch_bounds__(256) void gemm_ldsm(
    const float* __restrict__ A, const float* __restrict__ Bm, float* __restrict__ C,
    int M, int N, int K,
    int divA, int modA, long long sA, int divB, int modB, long long sB, long long sC,
    const float* __restrict__ bias, float alpha, int flags)
{
    constexpr int BM = 128, BN = 128, BK = 32;
    int z = blockIdx.z;
    A  += (long long)((z / divA) % modA) * sA;
    Bm += (long long)((z / divB) % modB) * sB;
    C  += (long long)z * sC;

    const int row0 = blockIdx.y * BM;
    const int col0 = blockIdx.x * BN;

    // Fully-masked causal block: skip compute entirely.
    if ((flags & FLAG_CMASK) && col0 > row0 + BM - 1) {
        for (int i = threadIdx.x; i < BM * BN; i += 256) {
            int r = i >> 7, c = i & 127;
            C[(long long)(row0 + r) * N + (col0 + c)] = -1e30f;
        }
        return;
    }

    __shared__ uint32_t As[128 * 32];
    __shared__ uint32_t Bs[128 * 32];

    const int tid  = threadIdx.x;
    const int lane = tid & 31, wid = tid >> 5;
    const int wm = wid & 3, wn = wid >> 2;          // warp at (wm*32, wn*64)
    const int g = lane >> 2, tig = lane & 3;        // mma groupID / thread-in-group
    const int r8 = lane & 7, q = lane >> 3;         // ldmatrix addressing

    const uint32_t saA = (uint32_t)__cvta_generic_to_shared(As);
    const uint32_t saB = (uint32_t)__cvta_generic_to_shared(Bs);

    // ldmatrix base addresses (byte): row*128 + ((row&7 ^ kbit)<<4); per-kstep XOR (ks<<5)
    uint32_t aBase[2], bBase[4];
    #pragma unroll
    for (int mt = 0; mt < 2; mt++) {
        int row = wm * 32 + mt * 16 + (q & 1) * 8 + r8;
        aBase[mt] = saA + row * 128 + (((row & 7) ^ (q >> 1)) << 4);
    }
    #pragma unroll
    for (int p = 0; p < 4; p++) {
        int row = wn * 64 + p * 16 + (q >> 1) * 8 + r8;
        bBase[p] = saB + row * 128 + (((row & 7) ^ (q & 1)) << 4);
    }

    float acc[16][4];
    #pragma unroll
    for (int i = 0; i < 16; i++)
        #pragma unroll
        for (int j = 0; j < 4; j++) acc[i][j] = 0.0f;

    int Kend = K;
    if (flags & FLAG_CK) Kend = min(K, row0 + BM);   // S rows beyond diag are exact 0

    for (int k0 = 0; k0 < Kend; k0 += BK) {
        // --- stage A and B tiles [128 x 32], cvt.rna to tf32, swizzled STS.128 ---
        #pragma unroll
        for (int i = 0; i < 4; i++) {
            int s = tid + i * 256;                   // 1024 float4 slots each
            int row = s >> 3, grp = s & 7;
            int sw = row * 32 + ((grp ^ (row & 7)) << 2);
            float4 va = *(const float4*)(A + (long long)(row0 + row) * K + k0 + grp * 4);
            uint4 ta = { f2tf32(va.x), f2tf32(va.y), f2tf32(va.z), f2tf32(va.w) };
            *(uint4*)&As[sw] = ta;
            float4 vb = *(const float4*)(Bm + (long long)(col0 + row) * K + k0 + grp * 4);
            uint4 tb = { f2tf32(vb.x), f2tf32(vb.y), f2tf32(vb.z), f2tf32(vb.w) };
            *(uint4*)&Bs[sw] = tb;
        }
        __syncthreads();

        #pragma unroll
        for (int ks = 0; ks < 4; ks++) {             // k = ks*8
            const uint32_t kx = (uint32_t)ks << 5;
            uint32_t afr[2][4], bfr[4][4];
            ldsm4(afr[0], aBase[0] ^ kx);
            ldsm4(afr[1], aBase[1] ^ kx);
            #pragma unroll
            for (int p = 0; p < 4; p++) ldsm4(bfr[p], bBase[p] ^ kx);
            #pragma unroll
            for (int mt = 0; mt < 2; mt++)
                #pragma unroll
                for (int nt = 0; nt < 8; nt++)
                    mma_tf32(acc[mt * 8 + nt], afr[mt], &bfr[nt >> 1][(nt & 1) * 2]);
        }
        __syncthreads();
    }

    // ---------------- epilogue (float2 stores) ----------------
    #pragma unroll
    for (int mt = 0; mt < 2; mt++) {
        #pragma unroll
        for (int nt = 0; nt < 8; nt++) {
            float* a4 = acc[mt * 8 + nt];
            int rb = row0 + wm * 32 + mt * 16 + g;
            int cb = col0 + wn * 64 + nt * 8 + tig * 2;
            #pragma unroll
            for (int half = 0; half < 2; half++) {
                int r = rb + half * 8;
                float v0 = a4[half * 2]     * alpha;
                float v1 = a4[half * 2 + 1] * alpha;
                if (bias) { v0 += bias[cb]; v1 += bias[cb + 1]; }
                if (flags & FLAG_RELU) { v0 = fmaxf(v0, 0.0f); v1 = fmaxf(v1, 0.0f); }
                if (flags & FLAG_CMASK) {
                    if (cb     > r) v0 = -1e30f;
                    if (cb + 1 > r) v1 = -1e30f;
                }
                float2* p = (float2*)(C + (long long)r * N + cb);
                if (flags & FLAG_ACCUM) {
                    float2 o = *p;
                    o.x += v0; o.y += v1;
                    *p = o;
                } else {
                    *p = make_float2(v0, v1);
                }
            }
        }
    }
}

// ---------------- host orchestration ----------------
extern "C" void kernel_launch(void* const* d_in, const int* in_sizes, int n_in,
                              void* d_out, int out_size) {
    const float* q    = (const float*)d_in[0];
    const float* k    = (const float*)d_in[1];
    const float* v    = (const float*)d_in[2];
    const float* Wq_s = (const float*)d_in[3];
    const float* Wk_s = (const float*)d_in[4];
    const float* Wv_s = (const float*)d_in[5];
    const float* Wq_c = (const float*)d_in[6];
    const float* Wk_c = (const float*)d_in[7];
    const float* Wv_c = (const float*)d_in[8];
    const float* W1   = (const float*)d_in[9];
    const float* b1   = (const float*)d_in[10];
    const float* W2   = (const float*)d_in[11];
    const float* b2   = (const float*)d_in[12];
    const float* g1   = (const float*)d_in[13];
    const float* be1  = (const float*)d_in[14];
    const float* g2   = (const float*)d_in[15];
    const float* be2  = (const float*)d_in[16];
    const float* g3   = (const float*)d_in[17];
    const float* be3  = (const float*)d_in[18];
    float* out = (float*)d_out;

    float *xn, *Qh, *Kh, *Vt, *S, *Wt;
    cudaGetSymbolAddress((void**)&xn, g_xn);
    cudaGetSymbolAddress((void**)&Qh, g_Qh);
    cudaGetSymbolAddress((void**)&Kh, g_Kh);
    cudaGetSymbolAddress((void**)&Vt, g_Vh);
    cudaGetSymbolAddress((void**)&S,  g_S);
    cudaGetSymbolAddress((void**)&Wt, g_Wt);

    const long long sLE = (long long)L_ * E_;  // per-batch activation stride
    const long long sED = (long long)E_ * D_;  // per-head weight stride
    const long long sLD = (long long)L_ * D_;  // per (b,h) Q/K/V stride
    const long long sLL = (long long)L_ * L_;  // per (b,h) score stride
    const int BIG = 1 << 30;
    const float scl = 0.044194173824159216f;   // 512^-0.5
    const long long WSZ = (long long)H_ * E_ * D_;

    float* Wqt = Wt;
    float* Wkt = Wt + WSZ;
    float* Wvt = Wt + 2 * WSZ;
    float* W1t = Wt;              // reused in FFN phase (attn weights done by then)
    float* W2t = Wt + (long long)FE_ * E_;

    const dim3 gT(E_ / 32, D_ / 32, H_);           // not used; per-call grids below
    const dim3 gQK(D_ / 128, L_ / 128, B_ * H_);   // (4,16,32)  Q/K proj + AV
    const dim3 gVt(L_ / 128, D_ / 128, B_ * H_);   // (16,4,32)  transposed V proj
    const dim3 gSc(L_ / 128, L_ / 128, B_ * H_);   // (16,16,32) scores

    // ===== Block 1: pre-norm causal self-attention =====
    transpose_kernel<<<dim3(D_ / 32, E_ / 32, H_), 256>>>(Wq_s, Wqt, E_, D_);
    transpose_kernel<<<dim3(D_ / 32, E_ / 32, H_), 256>>>(Wk_s, Wkt, E_, D_);
    transpose_kernel<<<dim3(D_ / 32, E_ / 32, H_), 256>>>(Wv_s, Wvt, E_, D_);
    ln_kernel<<<B_ * L_, 256>>>(q, g1, be1, xn);
    // Qh[b,h] = xn[b] @ Wqt[h]^T   (A=[L][E], B=[D][E])
    gemm_ldsm<<<gQK, 256>>>(xn, Wqt, Qh, L_, D_, E_, H_, B_, sLE, 1, H_, sED, sLD, nullptr, 1.f, 0);
    gemm_ldsm<<<gQK, 256>>>(xn, Wkt, Kh, L_, D_, E_, H_, B_, sLE, 1, H_, sED, sLD, nullptr, 1.f, 0);
    // Vt[b,h] = Wvt[h] @ xn[b]^T   (A=[D][E], B=[L][E]) -> [D][L]
    gemm_ldsm<<<gVt, 256>>>(Wvt, xn, Vt, D_, L_, E_, 1, H_, sED, H_, B_, sLE, sLD, nullptr, 1.f, 0);
    // S = scl * Qh @ Kh^T (causal)
    gemm_ldsm<<<gSc, 256>>>(Qh, Kh, S, L_, L_, D_, 1, BIG, sLD, 1, BIG, sLD, sLL, nullptr, scl, FLAG_CMASK);
    softmax_kernel<<<B_ * H_ * L_, 256>>>(S);
    // O = S @ Vt^T  (A=[L][L], B=[D][L]) with K capped at diag
    gemm_ldsm<<<gQK, 256>>>(S, Vt, Qh, L_, D_, L_, 1, BIG, sLL, 1, BIG, sLD, sLD, nullptr, 1.f, FLAG_CK);
    add_mean_kernel<<<(B_ * L_ * E_) / 256, 256>>>(q, Qh, out);   // out = q + mean_h(O)

    // ===== Block 2: pre-norm cross-attention (only queries normed) =====
    transpose_kernel<<<dim3(D_ / 32, E_ / 32, H_), 256>>>(Wq_c, Wqt, E_, D_);
    transpose_kernel<<<dim3(D_ / 32, E_ / 32, H_), 256>>>(Wk_c, Wkt, E_, D_);
    transpose_kernel<<<dim3(D_ / 32, E_ / 32, H_), 256>>>(Wv_c, Wvt, E_, D_);
    ln_kernel<<<B_ * L_, 256>>>(out, g2, be2, xn);
    gemm_ldsm<<<gQK, 256>>>(xn, Wqt, Qh, L_, D_, E_, H_, B_, sLE, 1, H_, sED, sLD, nullptr, 1.f, 0);
    gemm_ldsm<<<gQK, 256>>>(k,  Wkt, Kh, L_, D_, E_, H_, B_, sLE, 1, H_, sED, sLD, nullptr, 1.f, 0);
    gemm_ldsm<<<gVt, 256>>>(Wvt, v, Vt, D_, L_, E_, 1, H_, sED, H_, B_, sLE, sLD, nullptr, 1.f, 0);
    gemm_ldsm<<<gSc, 256>>>(Qh, Kh, S, L_, L_, D_, 1, BIG, sLD, 1, BIG, sLD, sLL, nullptr, scl, 0);
    softmax_kernel<<<B_ * H_ * L_, 256>>>(S);
    gemm_ldsm<<<gQK, 256>>>(S, Vt, Qh, L_, D_, L_, 1, BIG, sLL, 1, BIG, sLD, sLD, nullptr, 1.f, 0);
    add_mean_kernel<<<(B_ * L_ * E_) / 256, 256>>>(out, Qh, out); // out += mean_h(O)

    // ===== Block 3: FFN =====
    transpose_kernel<<<dim3(FE_ / 32, E_ / 32, 1), 256>>>(W1, W1t, E_, FE_);
    transpose_kernel<<<dim3(E_ / 32, FE_ / 32, 1), 256>>>(W2, W2t, FE_, E_);
    ln_kernel<<<B_ * L_, 256>>>(out, g3, be3, xn);
    // hidden = relu(xn @ W1t^T + b1), stored in S scratch: [B*L, 4E]
    gemm_ldsm<<<dim3(FE_ / 128, (B_ * L_) / 128, 1), 256>>>(
        xn, W1t, S, B_ * L_, FE_, E_, 1, 1, 0, 1, 1, 0, 0, b1, 1.f, FLAG_RELU);
    // out += hidden @ W2t^T + b2
    gemm_ldsm<<<dim3(E_ / 128, (B_ * L_) / 128, 1), 256>>>(
        S, W2t, out, B_ * L_, E_, FE_, 1, 1, 0, 1, 1, 0, 0, b2, 1.f, FLAG_ACCUM);
}

// round 5
// speedup vs baseline: 3.2330x; 1.4996x over previous
#include <cuda_runtime.h>
#include <math.h>
#include <stdint.h>

// Problem constants (fixed shapes from reference)
constexpr int B_ = 4, L_ = 2048, E_ = 512, H_ = 8, D_ = 512, FE_ = 2048; // FE = FW*E

#define FLAG_RELU    1
#define FLAG_ACCUM   2
#define FLAG_CMASK   4
#define FLAG_CK      8
#define FLAG_TF32OUT 16

// ---------------- static scratch (allocation-free) ----------------
__device__ float g_xn[(size_t)B_ * L_ * E_];              //  16.8 MB
__device__ float g_Qh[(size_t)B_ * H_ * L_ * D_];         // 134 MB (also per-head attn output)
__device__ float g_Kh[(size_t)B_ * H_ * L_ * D_];         // 134 MB
__device__ float g_Vh[(size_t)B_ * H_ * L_ * D_];         // 134 MB (stores V^T per head: [D][L])
__device__ float g_S [(size_t)B_ * H_ * L_ * L_];         // 537 MB (also FFN hidden)
__device__ float g_Wt[(size_t)3 * H_ * E_ * D_];          //  25 MB transposed weights
__device__ float g_kv[(size_t)2 * B_ * L_ * E_];          //  33.6 MB tf32-rounded k,v

// ---------------- tf32 helper ----------------
__device__ __forceinline__ uint32_t f2tf32(float x) {
    uint32_t r;
    asm("cvt.rna.tf32.f32 %0, %1;" : "=r"(r) : "f"(x));
    return r;
}
__device__ __forceinline__ float rna32(float x) { return __uint_as_float(f2tf32(x)); }

// ---------------- block reductions (256 threads) ----------------
__device__ __forceinline__ float blk_sum(float v) {
    __shared__ float s[9];
    #pragma unroll
    for (int o = 16; o > 0; o >>= 1) v += __shfl_xor_sync(0xffffffffu, v, o);
    int w = threadIdx.x >> 5, lane = threadIdx.x & 31;
    __syncthreads();
    if (lane == 0) s[w] = v;
    __syncthreads();
    if (w == 0) {
        float t = (lane < 8) ? s[lane] : 0.0f;
        #pragma unroll
        for (int o = 4; o > 0; o >>= 1) t += __shfl_xor_sync(0xffffffffu, t, o);
        if (lane == 0) s[8] = t;
    }
    __syncthreads();
    return s[8];
}

__device__ __forceinline__ float blk_max(float v) {
    __shared__ float s[9];
    #pragma unroll
    for (int o = 16; o > 0; o >>= 1) v = fmaxf(v, __shfl_xor_sync(0xffffffffu, v, o));
    int w = threadIdx.x >> 5, lane = threadIdx.x & 31;
    __syncthreads();
    if (lane == 0) s[w] = v;
    __syncthreads();
    if (w == 0) {
        float t = (lane < 8) ? s[lane] : -3.4e38f;
        #pragma unroll
        for (int o = 4; o > 0; o >>= 1) t = fmaxf(t, __shfl_xor_sync(0xffffffffu, t, o));
        if (lane == 0) s[8] = t;
    }
    __syncthreads();
    return s[8];
}

// ---------------- LayerNorm (output rounded to tf32: feeds GEMMs) ----------------
__global__ void ln_kernel(const float* __restrict__ x, const float* __restrict__ g,
                          const float* __restrict__ b, float* __restrict__ y) {
    long long row = blockIdx.x;
    const float* xr = x + row * E_;
    float*       yr = y + row * E_;
    int t = threadIdx.x;
    float a0 = xr[t], a1 = xr[t + 256];
    float mean = blk_sum(a0 + a1) * (1.0f / E_);
    float d0 = a0 - mean, d1 = a1 - mean;
    float var = blk_sum(d0 * d0 + d1 * d1) * (1.0f / E_);
    float inv = rsqrtf(var + 1e-5f);
    yr[t]       = rna32(d0 * inv * g[t]       + b[t]);
    yr[t + 256] = rna32(d1 * inv * g[t + 256] + b[t + 256]);
}

// ---------------- Softmax (output rounded to tf32: feeds AV GEMM) ----------------
__global__ void softmax_kernel(float* __restrict__ S) {
    long long row = blockIdx.x;
    float* r = S + row * (long long)L_;
    int t = threadIdx.x;
    float v[8];
    float mx = -3.4e38f;
    #pragma unroll
    for (int i = 0; i < 8; i++) { v[i] = r[t + i * 256]; mx = fmaxf(mx, v[i]); }
    mx = blk_max(mx);
    float s = 0.0f;
    #pragma unroll
    for (int i = 0; i < 8; i++) { v[i] = __expf(v[i] - mx); s += v[i]; }
    s = blk_sum(s);
    float inv = 1.0f / s;
    #pragma unroll
    for (int i = 0; i < 8; i++) r[t + i * 256] = rna32(v[i] * inv);
}

// ---------------- out[idx] = base[idx] + mean_h Oh[b,h,l,e] (fp32) ----------------
__global__ void add_mean_kernel(const float* __restrict__ base, const float* __restrict__ Oh,
                                float* __restrict__ out) {
    long long idx = (long long)blockIdx.x * 256 + threadIdx.x;       // over B*L*E
    long long b   = idx >> 20;                                       // L*E = 2^20
    long long rem = idx & ((1LL << 20) - 1);
    const float* p = Oh + b * ((long long)H_ * L_ * D_) + rem;
    float s = 0.0f;
    #pragma unroll
    for (int h = 0; h < H_; h++) s += p[(long long)h * L_ * D_];
    out[idx] = base[idx] + s * (1.0f / H_);
}

// ---------------- elementwise rna copy (raw k,v -> tf32 values) ----------------
__global__ void rna_copy_kernel(const float* __restrict__ X, float* __restrict__ Y) {
    long long i = ((long long)blockIdx.x * 256 + threadIdx.x) * 4;
    float4 v = *(const float4*)(X + i);
    v.x = rna32(v.x); v.y = rna32(v.y); v.z = rna32(v.z); v.w = rna32(v.w);
    *(float4*)(Y + i) = v;
}

// ---------------- Batched transpose (+rna): Y[z][c][r] = rna(X[z][r][c]) ----------
__global__ void transpose_kernel(const float* __restrict__ X, float* __restrict__ Y,
                                 int R, int Cc) {
    __shared__ float t[32][33];
    long long zo = (long long)blockIdx.z * R * Cc;
    int c0 = blockIdx.x * 32, r0 = blockIdx.y * 32;
    int tx = threadIdx.x & 31, ty = threadIdx.x >> 5;   // 256 threads, ty=0..7
    #pragma unroll
    for (int i = 0; i < 32; i += 8)
        t[ty + i][tx] = X[zo + (long long)(r0 + ty + i) * Cc + c0 + tx];
    __syncthreads();
    #pragma unroll
    for (int i = 0; i < 32; i += 8)
        Y[zo + (long long)(c0 + ty + i) * R + r0 + tx] = rna32(t[tx][ty + i]);
}

// ---------------- mma / ldmatrix / cp.async helpers ----------------
__device__ __forceinline__ void mma_tf32(float d[4], const uint32_t a[4], const uint32_t b[2]) {
    asm volatile(
        "mma.sync.aligned.m16n8k8.row.col.f32.tf32.tf32.f32 "
        "{%0,%1,%2,%3}, {%4,%5,%6,%7}, {%8,%9}, {%0,%1,%2,%3};"
        : "+f"(d[0]), "+f"(d[1]), "+f"(d[2]), "+f"(d[3])
        : "r"(a[0]), "r"(a[1]), "r"(a[2]), "r"(a[3]), "r"(b[0]), "r"(b[1]));
}

__device__ __forceinline__ void ldsm4(uint32_t r[4], uint32_t addr) {
    asm volatile("ldmatrix.sync.aligned.m8n8.x4.shared.b16 {%0,%1,%2,%3}, [%4];"
                 : "=r"(r[0]), "=r"(r[1]), "=r"(r[2]), "=r"(r[3]) : "r"(addr));
}

__device__ __forceinline__ void cp16(uint32_t dst, const void* src) {
    asm volatile("cp.async.cg.shared.global [%0], [%1], 16;" :: "r"(dst), "l"(src));
}

// ---------------- Tensor-core GEMM (all-TRANSB, cp.async 2-stage pipeline) ------
// C[z] = alpha * A[z] * B[z]^T (+bias)(relu)(+C)(causal)(tf32-round-out)
// A: [M][K], B: [N][K] row-major; values in gmem are ALREADY tf32-rounded.
// BM=BN=128, BK=32. 256 threads = 8 warps (4x2), warp tile 32x64, m16n8k8 tf32.
// SMEM (dynamic 64KB): A stages at 0/16KB... layout below; swizzle grp^(row&7).
__global__ __launch_bounds__(256) void gemm_cp(
    const float* __restrict__ A, const float* __restrict__ Bm, float* __restrict__ C,
    int M, int N, int K,
    int divA, int modA, long long sA, int divB, int modB, long long sB, long long sC,
    const float* __restrict__ bias, float alpha, int flags)
{
    constexpr int BM = 128, BN = 128, BK = 32;
    extern __shared__ uint32_t smem[];
    int z = blockIdx.z;
    A  += (long long)((z / divA) % modA) * sA;
    Bm += (long long)((z / divB) % modB) * sB;
    C  += (long long)z * sC;

    const int row0 = blockIdx.y * BM;
    const int col0 = blockIdx.x * BN;

    // Fully-masked causal block: skip compute entirely.
    if ((flags & FLAG_CMASK) && col0 > row0 + BM - 1) {
        for (int i = threadIdx.x; i < BM * BN; i += 256) {
            int r = i >> 7, c = i & 127;
            C[(long long)(row0 + r) * N + (col0 + c)] = -1e30f;
        }
        return;
    }

    const int tid  = threadIdx.x;
    const int lane = tid & 31, wid = tid >> 5;
    const int wm = wid & 3, wn = wid >> 2;          // warp at (wm*32, wn*64)
    const int g = lane >> 2, tig = lane & 3;        // mma groupID / thread-in-group
    const int r8 = lane & 7, q = lane >> 3;         // ldmatrix addressing

    const uint32_t sb = (uint32_t)__cvta_generic_to_shared(smem);
    // stage s: A tile bytes [s*16384, +16KB), B tile bytes [32768 + s*16384, +16KB)

    // cp.async destination offsets (bytes) for this thread's 4 A / 4 B slots
    uint32_t dstOff[4];
    const float *srcA[4], *srcB0 = nullptr; // srcB computed per-iter via row/grp too
    int rowA[4], grpA[4];
    #pragma unroll
    for (int i = 0; i < 4; i++) {
        int s = tid + i * 256;                      // 1024 float4 slots
        int row = s >> 3, grp = s & 7;
        rowA[i] = row; grpA[i] = grp;
        dstOff[i] = (uint32_t)((row * 32 + ((grp ^ (row & 7)) << 2)) * 4);
    }
    (void)srcA; (void)srcB0;

    // ldmatrix relative base addresses (bytes within a stage's tile)
    uint32_t aRel[2], bRel[4];
    #pragma unroll
    for (int mt = 0; mt < 2; mt++) {
        int row = wm * 32 + mt * 16 + (q & 1) * 8 + r8;
        aRel[mt] = (uint32_t)(row * 128 + (((row & 7) ^ (q >> 1)) << 4));
    }
    #pragma unroll
    for (int p = 0; p < 4; p++) {
        int row = wn * 64 + p * 16 + (q >> 1) * 8 + r8;
        bRel[p] = (uint32_t)(row * 128 + (((row & 7) ^ (q & 1)) << 4));
    }

    float acc[16][4];
    #pragma unroll
    for (int i = 0; i < 16; i++)
        #pragma unroll
        for (int j = 0; j < 4; j++) acc[i][j] = 0.0f;

    int Kend = K;
    if (flags & FLAG_CK) Kend = min(K, row0 + BM);   // S rows beyond diag are exact 0
    const int nk = Kend / BK;

    // issue stage loads for chunk k0 into stage stg
    auto issue = [&](int k0, int stg) {
        uint32_t aBase = sb + (uint32_t)stg * 16384u;
        uint32_t bBase = sb + 32768u + (uint32_t)stg * 16384u;
        #pragma unroll
        for (int i = 0; i < 4; i++) {
            cp16(aBase + dstOff[i], A  + (long long)(row0 + rowA[i]) * K + k0 + grpA[i] * 4);
            cp16(bBase + dstOff[i], Bm + (long long)(col0 + rowA[i]) * K + k0 + grpA[i] * 4);
        }
        asm volatile("cp.async.commit_group;");
    };

    issue(0, 0);
    for (int it = 0; it < nk; it++) {
        const int cur = it & 1;
        asm volatile("cp.async.wait_group 0;");
        __syncthreads();
        if (it + 1 < nk) issue((it + 1) * BK, cur ^ 1);

        const uint32_t aStage = sb + (uint32_t)cur * 16384u;
        const uint32_t bStage = sb + 32768u + (uint32_t)cur * 16384u;
        #pragma unroll
        for (int ks = 0; ks < 4; ks++) {             // k = ks*8
            const uint32_t kx = (uint32_t)ks << 5;
            uint32_t afr[2][4], bfr[4][4];
            ldsm4(afr[0], (aStage + aRel[0]) ^ kx);
            ldsm4(afr[1], (aStage + aRel[1]) ^ kx);
            #pragma unroll
            for (int p = 0; p < 4; p++) ldsm4(bfr[p], (bStage + bRel[p]) ^ kx);
            #pragma unroll
            for (int mt = 0; mt < 2; mt++)
                #pragma unroll
                for (int nt = 0; nt < 8; nt++)
                    mma_tf32(acc[mt * 8 + nt], afr[mt], &bfr[nt >> 1][(nt & 1) * 2]);
        }
        __syncthreads();
    }

    // ---------------- epilogue (float2 stores) ----------------
    #pragma unroll
    for (int mt = 0; mt < 2; mt++) {
        #pragma unroll
        for (int nt = 0; nt < 8; nt++) {
            float* a4 = acc[mt * 8 + nt];
            int rb = row0 + wm * 32 + mt * 16 + g;
            int cb = col0 + wn * 64 + nt * 8 + tig * 2;
            #pragma unroll
            for (int half = 0; half < 2; half++) {
                int r = rb + half * 8;
                float v0 = a4[half * 2]     * alpha;
                float v1 = a4[half * 2 + 1] * alpha;
                if (bias) { v0 += bias[cb]; v1 += bias[cb + 1]; }
                if (flags & FLAG_RELU) { v0 = fmaxf(v0, 0.0f); v1 = fmaxf(v1, 0.0f); }
                if (flags & FLAG_CMASK) {
                    if (cb     > r) v0 = -1e30f;
                    if (cb + 1 > r) v1 = -1e30f;
                }
                if (flags & FLAG_TF32OUT) { v0 = rna32(v0); v1 = rna32(v1); }
                float2* p = (float2*)(C + (long long)r * N + cb);
                if (flags & FLAG_ACCUM) {
                    float2 o = *p;
                    o.x += v0; o.y += v1;
                    *p = o;
                } else {
                    *p = make_float2(v0, v1);
                }
            }
        }
    }
}

// ---------------- host orchestration ----------------
extern "C" void kernel_launch(void* const* d_in, const int* in_sizes, int n_in,
                              void* d_out, int out_size) {
    const float* q    = (const float*)d_in[0];
    const float* k    = (const float*)d_in[1];
    const float* v    = (const float*)d_in[2];
    const float* Wq_s = (const float*)d_in[3];
    const float* Wk_s = (const float*)d_in[4];
    const float* Wv_s = (const float*)d_in[5];
    const float* Wq_c = (const float*)d_in[6];
    const float* Wk_c = (const float*)d_in[7];
    const float* Wv_c = (const float*)d_in[8];
    const float* W1   = (const float*)d_in[9];
    const float* b1   = (const float*)d_in[10];
    const float* W2   = (const float*)d_in[11];
    const float* b2   = (const float*)d_in[12];
    const float* g1   = (const float*)d_in[13];
    const float* be1  = (const float*)d_in[14];
    const float* g2   = (const float*)d_in[15];
    const float* be2  = (const float*)d_in[16];
    const float* g3   = (const float*)d_in[17];
    const float* be3  = (const float*)d_in[18];
    float* out = (float*)d_out;

    float *xn, *Qh, *Kh, *Vt, *S, *Wt, *kv;
    cudaGetSymbolAddress((void**)&xn, g_xn);
    cudaGetSymbolAddress((void**)&Qh, g_Qh);
    cudaGetSymbolAddress((void**)&Kh, g_Kh);
    cudaGetSymbolAddress((void**)&Vt, g_Vh);
    cudaGetSymbolAddress((void**)&S,  g_S);
    cudaGetSymbolAddress((void**)&Wt, g_Wt);
    cudaGetSymbolAddress((void**)&kv, g_kv);

    static bool attr_done = false;
    if (!attr_done) {
        cudaFuncSetAttribute(gemm_cp, cudaFuncAttributeMaxDynamicSharedMemorySize, 65536);
        attr_done = true;
    }
    const int SMB = 65536;

    const long long sLE = (long long)L_ * E_;  // per-batch activation stride
    const long long sED = (long long)E_ * D_;  // per-head weight stride
    const long long sLD = (long long)L_ * D_;  // per (b,h) Q/K/V stride
    const long long sLL = (long long)L_ * L_;  // per (b,h) score stride
    const int BIG = 1 << 30;
    const float scl = 0.044194173824159216f;   // 512^-0.5
    const long long WSZ = (long long)H_ * E_ * D_;

    float* Wqt = Wt;
    float* Wkt = Wt + WSZ;
    float* Wvt = Wt + 2 * WSZ;
    float* W1t = Wt;              // reused in FFN phase (attn weights done by then)
    float* W2t = Wt + (long long)FE_ * E_;
    float* kr  = kv;              // tf32-rounded k
    float* vr  = kv + sLE * B_;   // tf32-rounded v

    const dim3 gQK(D_ / 128, L_ / 128, B_ * H_);   // (4,16,32)  Q/K proj + AV
    const dim3 gVt(L_ / 128, D_ / 128, B_ * H_);   // (16,4,32)  transposed V proj
    const dim3 gSc(L_ / 128, L_ / 128, B_ * H_);   // (16,16,32) scores

    // ===== Block 1: pre-norm causal self-attention =====
    transpose_kernel<<<dim3(D_ / 32, E_ / 32, H_), 256>>>(Wq_s, Wqt, E_, D_);
    transpose_kernel<<<dim3(D_ / 32, E_ / 32, H_), 256>>>(Wk_s, Wkt, E_, D_);
    transpose_kernel<<<dim3(D_ / 32, E_ / 32, H_), 256>>>(Wv_s, Wvt, E_, D_);
    rna_copy_kernel<<<(B_ * L_ * E_) / 1024, 256>>>(k, kr);
    rna_copy_kernel<<<(B_ * L_ * E_) / 1024, 256>>>(v, vr);
    ln_kernel<<<B_ * L_, 256>>>(q, g1, be1, xn);
    // Qh[b,h] = xn[b] @ Wqt[h]^T   (A=[L][E], B=[D][E])
    gemm_cp<<<gQK, 256, SMB>>>(xn, Wqt, Qh, L_, D_, E_, H_, B_, sLE, 1, H_, sED, sLD, nullptr, 1.f, FLAG_TF32OUT);
    gemm_cp<<<gQK, 256, SMB>>>(xn, Wkt, Kh, L_, D_, E_, H_, B_, sLE, 1, H_, sED, sLD, nullptr, 1.f, FLAG_TF32OUT);
    // Vt[b,h] = Wvt[h] @ xn[b]^T   (A=[D][E], B=[L][E]) -> [D][L]
    gemm_cp<<<gVt, 256, SMB>>>(Wvt, xn, Vt, D_, L_, E_, 1, H_, sED, H_, B_, sLE, sLD, nullptr, 1.f, FLAG_TF32OUT);
    // S = scl * Qh @ Kh^T (causal)
    gemm_cp<<<gSc, 256, SMB>>>(Qh, Kh, S, L_, L_, D_, 1, BIG, sLD, 1, BIG, sLD, sLL, nullptr, scl, FLAG_CMASK);
    softmax_kernel<<<B_ * H_ * L_, 256>>>(S);
    // O = S @ Vt^T  (A=[L][L], B=[D][L]) with K capped at diag
    gemm_cp<<<gQK, 256, SMB>>>(S, Vt, Qh, L_, D_, L_, 1, BIG, sLL, 1, BIG, sLD, sLD, nullptr, 1.f, FLAG_CK);
    add_mean_kernel<<<(B_ * L_ * E_) / 256, 256>>>(q, Qh, out);   // out = q + mean_h(O)

    // ===== Block 2: pre-norm cross-attention (only queries normed) =====
    transpose_kernel<<<dim3(D_ / 32, E_ / 32, H_), 256>>>(Wq_c, Wqt, E_, D_);
    transpose_kernel<<<dim3(D_ / 32, E_ / 32, H_), 256>>>(Wk_c, Wkt, E_, D_);
    transpose_kernel<<<dim3(D_ / 32, E_ / 32, H_), 256>>>(Wv_c, Wvt, E_, D_);
    ln_kernel<<<B_ * L_, 256>>>(out, g2, be2, xn);
    gemm_cp<<<gQK, 256, SMB>>>(xn, Wqt, Qh, L_, D_, E_, H_, B_, sLE, 1, H_, sED, sLD, nullptr, 1.f, FLAG_TF32OUT);
    gemm_cp<<<gQK, 256, SMB>>>(kr, Wkt, Kh, L_, D_, E_, H_, B_, sLE, 1, H_, sED, sLD, nullptr, 1.f, FLAG_TF32OUT);
    gemm_cp<<<gVt, 256, SMB>>>(Wvt, vr, Vt, D_, L_, E_, 1, H_, sED, H_, B_, sLE, sLD, nullptr, 1.f, FLAG_TF32OUT);
    gemm_cp<<<gSc, 256, SMB>>>(Qh, Kh, S, L_, L_, D_, 1, BIG, sLD, 1, BIG, sLD, sLL, nullptr, scl, 0);
    softmax_kernel<<<B_ * H_ * L_, 256>>>(S);
    gemm_cp<<<gQK, 256, SMB>>>(S, Vt, Qh, L_, D_, L_, 1, BIG, sLL, 1, BIG, sLD, sLD, nullptr, 1.f, 0);
    add_mean_kernel<<<(B_ * L_ * E_) / 256, 256>>>(out, Qh, out); // out += mean_h(O)

    // ===== Block 3: FFN =====
    transpose_kernel<<<dim3(FE_ / 32, E_ / 32, 1), 256>>>(W1, W1t, E_, FE_);
    transpose_kernel<<<dim3(E_ / 32, FE_ / 32, 1), 256>>>(W2, W2t, FE_, E_);
    ln_kernel<<<B_ * L_, 256>>>(out, g3, be3, xn);
    // hidden = relu(xn @ W1t^T + b1) -> tf32, stored in S scratch: [B*L, 4E]
    gemm_cp<<<dim3(FE_ / 128, (B_ * L_) / 128, 1), 256, SMB>>>(
        xn, W1t, S, B_ * L_, FE_, E_, 1, 1, 0, 1, 1, 0, 0, b1, 1.f, FLAG_RELU | FLAG_TF32OUT);
    // out += hidden @ W2t^T + b2
    gemm_cp<<<dim3(E_ / 128, (B_ * L_) / 128, 1), 256, SMB>>>(
        S, W2t, out, B_ * L_, E_, FE_, 1, 1, 0, 1, 1, 0, 0, b2, 1.f, FLAG_ACCUM);
}

// round 7
// speedup vs baseline: 5.4135x; 1.6744x over previous
#include <cuda_runtime.h>
#include <cuda_fp16.h>
#include <math.h>
#include <stdint.h>

// Problem constants (fixed shapes from reference)
constexpr int B_ = 4, L_ = 2048, E_ = 512, H_ = 8, D_ = 512, FE_ = 2048; // FE = FW*E

#define FLAG_RELU    1
#define FLAG_ACCUM   2
#define FLAG_CMASK   4
#define FLAG_CK      8
#define FLAG_OUTH    16   // write output as fp16 (feeds a later GEMM)

// ---------------- static scratch (allocation-free) ----------------
__device__ __half h_xn[(size_t)B_ * L_ * E_];             //   8.4 MB LN output (fp16)
__device__ __half h_Qh[(size_t)B_ * H_ * L_ * D_];        //  67 MB per-head Q (fp16)
__device__ __half h_Kh[(size_t)B_ * H_ * L_ * D_];        //  67 MB per-head K (fp16)
__device__ __half h_Vt[(size_t)B_ * H_ * L_ * D_];        //  67 MB per-head V^T [D][L] (fp16)
__device__ float  g_S [(size_t)B_ * H_ * L_ * L_];        // 537 MB scores (fp32)
__device__ __half h_P [(size_t)B_ * H_ * L_ * L_];        // 268 MB probs (fp16, also FFN hidden)
__device__ float  g_O [(size_t)B_ * H_ * L_ * D_];        // 134 MB attn out (fp32)
__device__ __half h_Wt[(size_t)3 * H_ * E_ * D_];         //  12.6 MB transposed weights (fp16)
__device__ __half h_kv[(size_t)2 * B_ * L_ * E_];         //  16.8 MB fp16 k,v

// ---------------- block reductions (256 threads) ----------------
__device__ __forceinline__ float blk_sum(float v) {
    __shared__ float s[9];
    #pragma unroll
    for (int o = 16; o > 0; o >>= 1) v += __shfl_xor_sync(0xffffffffu, v, o);
    int w = threadIdx.x >> 5, lane = threadIdx.x & 31;
    __syncthreads();
    if (lane == 0) s[w] = v;
    __syncthreads();
    if (w == 0) {
        float t = (lane < 8) ? s[lane] : 0.0f;
        #pragma unroll
        for (int o = 4; o > 0; o >>= 1) t += __shfl_xor_sync(0xffffffffu, t, o);
        if (lane == 0) s[8] = t;
    }
    __syncthreads();
    return s[8];
}

__device__ __forceinline__ float blk_max(float v) {
    __shared__ float s[9];
    #pragma unroll
    for (int o = 16; o > 0; o >>= 1) v = fmaxf(v, __shfl_xor_sync(0xffffffffu, v, o));
    int w = threadIdx.x >> 5, lane = threadIdx.x & 31;
    __syncthreads();
    if (lane == 0) s[w] = v;
    __syncthreads();
    if (w == 0) {
        float t = (lane < 8) ? s[lane] : -3.4e38f;
        #pragma unroll
        for (int o = 4; o > 0; o >>= 1) t = fmaxf(t, __shfl_xor_sync(0xffffffffu, t, o));
        if (lane == 0) s[8] = t;
    }
    __syncthreads();
    return s[8];
}

// ---------------- LayerNorm (fp16 output: feeds GEMMs) ----------------
__global__ void ln_kernel(const float* __restrict__ x, const float* __restrict__ g,
                          const float* __restrict__ b, __half* __restrict__ y) {
    long long row = blockIdx.x;
    const float* xr = x + row * E_;
    __half*      yr = y + row * E_;
    int t = threadIdx.x;
    float a0 = xr[t], a1 = xr[t + 256];
    float mean = blk_sum(a0 + a1) * (1.0f / E_);
    float d0 = a0 - mean, d1 = a1 - mean;
    float var = blk_sum(d0 * d0 + d1 * d1) * (1.0f / E_);
    float inv = rsqrtf(var + 1e-5f);
    yr[t]       = __float2half_rn(d0 * inv * g[t]       + b[t]);
    yr[t + 256] = __float2half_rn(d1 * inv * g[t + 256] + b[t + 256]);
}

// ---------------- Softmax: fp32 scores in, fp16 probs out ----------------
__global__ void softmax_kernel(const float* __restrict__ S, __half* __restrict__ P) {
    long long row = blockIdx.x;
    const float* r = S + row * (long long)L_;
    __half*      p = P + row * (long long)L_;
    int t = threadIdx.x;
    float v[8];
    float mx = -3.4e38f;
    #pragma unroll
    for (int i = 0; i < 8; i++) { v[i] = r[t + i * 256]; mx = fmaxf(mx, v[i]); }
    mx = blk_max(mx);
    float s = 0.0f;
    #pragma unroll
    for (int i = 0; i < 8; i++) { v[i] = __expf(v[i] - mx); s += v[i]; }
    s = blk_sum(s);
    float inv = 1.0f / s;
    #pragma unroll
    for (int i = 0; i < 8; i++) p[t + i * 256] = __float2half_rn(v[i] * inv);
}

// ---------------- out[idx] = base[idx] + mean_h Oh[b,h,l,e] (fp32) ----------------
__global__ void add_mean_kernel(const float* __restrict__ base, const float* __restrict__ Oh,
                                float* __restrict__ out) {
    long long idx = (long long)blockIdx.x * 256 + threadIdx.x;       // over B*L*E
    long long b   = idx >> 20;                                       // L*E = 2^20
    long long rem = idx & ((1LL << 20) - 1);
    const float* p = Oh + b * ((long long)H_ * L_ * D_) + rem;
    float s = 0.0f;
    #pragma unroll
    for (int h = 0; h < H_; h++) s += p[(long long)h * L_ * D_];
    out[idx] = base[idx] + s * (1.0f / H_);
}

// ---------------- elementwise fp16 copy (raw k,v -> fp16) ----------------
__global__ void half_copy_kernel(const float* __restrict__ X, __half* __restrict__ Y) {
    long long i = ((long long)blockIdx.x * 256 + threadIdx.x) * 4;
    float4 v = *(const float4*)(X + i);
    __half2* y = (__half2*)(Y + i);
    y[0] = __floats2half2_rn(v.x, v.y);
    y[1] = __floats2half2_rn(v.z, v.w);
}

// ---------------- Batched transpose (+fp16): Y[z][c][r] = h(X[z][r][c]) ----------
__global__ void transpose_kernel(const float* __restrict__ X, __half* __restrict__ Y,
                                 int R, int Cc) {
    __shared__ float t[32][33];
    long long zo = (long long)blockIdx.z * R * Cc;
    int c0 = blockIdx.x * 32, r0 = blockIdx.y * 32;
    int tx = threadIdx.x & 31, ty = threadIdx.x >> 5;   // 256 threads, ty=0..7
    #pragma unroll
    for (int i = 0; i < 32; i += 8)
        t[ty + i][tx] = X[zo + (long long)(r0 + ty + i) * Cc + c0 + tx];
    __syncthreads();
    #pragma unroll
    for (int i = 0; i < 32; i += 8)
        Y[zo + (long long)(c0 + ty + i) * R + r0 + tx] = __float2half_rn(t[tx][ty + i]);
}

// ---------------- mma / ldmatrix / cp.async helpers ----------------
__device__ __forceinline__ void mma_f16(float d[4], const uint32_t a[4], const uint32_t b[2]) {
    asm volatile(
        "mma.sync.aligned.m16n8k16.row.col.f32.f16.f16.f32 "
        "{%0,%1,%2,%3}, {%4,%5,%6,%7}, {%8,%9}, {%0,%1,%2,%3};"
        : "+f"(d[0]), "+f"(d[1]), "+f"(d[2]), "+f"(d[3])
        : "r"(a[0]), "r"(a[1]), "r"(a[2]), "r"(a[3]), "r"(b[0]), "r"(b[1]));
}

__device__ __forceinline__ void ldsm4(uint32_t r[4], uint32_t addr) {
    asm volatile("ldmatrix.sync.aligned.m8n8.x4.shared.b16 {%0,%1,%2,%3}, [%4];"
                 : "=r"(r[0]), "=r"(r[1]), "=r"(r[2]), "=r"(r[3]) : "r"(addr));
}

__device__ __forceinline__ void cp16(uint32_t dst, const void* src) {
    asm volatile("cp.async.cg.shared.global [%0], [%1], 16;" :: "r"(dst), "l"(src));
}

// ---------------- fp16 tensor-core GEMM (all-TRANSB, cp.async 2-stage) ----------
// C[z] = alpha * A[z] * B[z]^T (+bias)(relu)(+C)(causal); output fp32 or fp16.
// A: [M][K], B: [N][K] row-major fp16. BM=BN=128, BK=64 (row = 128B = 8 x 16B grp).
// 256 threads = 8 warps (4x2), warp tile 32x64, mma m16n8k16 f16.f32.
// SMEM (dynamic 64KB): stage s at s*32768: A tile 16KB then B tile 16KB.
// Swizzle: 16B group g of row r stored at byte r*128 + ((g ^ (r&7))<<4).
__global__ __launch_bounds__(256) void gemm_h(
    const __half* __restrict__ A, const __half* __restrict__ Bm, void* __restrict__ Cv,
    int M, int N, int K,
    int divA, int modA, long long sA, int divB, int modB, long long sB, long long sC,
    const float* __restrict__ bias, float alpha, int flags)
{
    constexpr int BM = 128, BK = 64;
    extern __shared__ uint32_t smem[];
    int z = blockIdx.z;
    A  += (long long)((z / divA) % modA) * sA;
    Bm += (long long)((z / divB) % modB) * sB;
    float*  C  = (float*)Cv + (long long)z * sC;
    __half* Ch = (__half*)Cv + (long long)z * sC;

    const int row0 = blockIdx.y * BM;
    const int col0 = blockIdx.x * 128;

    // Fully-masked causal block: skip compute entirely (score GEMM is fp32-out).
    if ((flags & FLAG_CMASK) && col0 > row0 + BM - 1) {
        for (int i = threadIdx.x; i < 128 * 128; i += 256) {
            int r = i >> 7, c = i & 127;
            C[(long long)(row0 + r) * N + (col0 + c)] = -1e30f;
        }
        return;
    }

    const int tid  = threadIdx.x;
    const int lane = tid & 31, wid = tid >> 5;
    const int wm = wid & 3, wn = wid >> 2;          // warp at (wm*32, wn*64)
    const int g = lane >> 2, tig = lane & 3;        // mma groupID / thread-in-group
    const int r8 = lane & 7, q = lane >> 3;         // ldmatrix addressing

    const uint32_t sb = (uint32_t)__cvta_generic_to_shared(smem);

    // cp.async destinations: 1024 16B slots per operand tile; 4 per thread.
    uint32_t dstOff[4];
    int rowA[4], grpA[4];
    #pragma unroll
    for (int i = 0; i < 4; i++) {
        int s = tid + i * 256;
        int row = s >> 3, grp = s & 7;
        rowA[i] = row; grpA[i] = grp;
        dstOff[i] = (uint32_t)(row * 128 + ((grp ^ (row & 7)) << 4));
    }

    // ldmatrix relative base addresses (bytes within a stage's 16KB tile)
    uint32_t aRel[2], bRel[4];
    #pragma unroll
    for (int mt = 0; mt < 2; mt++) {
        int row = wm * 32 + mt * 16 + (q & 1) * 8 + r8;
        aRel[mt] = (uint32_t)(row * 128 + (((row & 7) ^ (q >> 1)) << 4));
    }
    #pragma unroll
    for (int p = 0; p < 4; p++) {
        int row = wn * 64 + p * 16 + (q >> 1) * 8 + r8;
        bRel[p] = (uint32_t)(row * 128 + (((row & 7) ^ (q & 1)) << 4));
    }

    float acc[16][4];
    #pragma unroll
    for (int i = 0; i < 16; i++)
        #pragma unroll
        for (int j = 0; j < 4; j++) acc[i][j] = 0.0f;

    int Kend = K;
    if (flags & FLAG_CK) Kend = min(K, row0 + BM);   // P cols beyond diag are exact 0
    const int nk = Kend / BK;

    auto issue = [&](int k0, int stg) {
        uint32_t aBase = sb + (uint32_t)stg * 32768u;
        uint32_t bBase = aBase + 16384u;
        #pragma unroll
        for (int i = 0; i < 4; i++) {
            cp16(aBase + dstOff[i], A  + (long long)(row0 + rowA[i]) * K + k0 + grpA[i] * 8);
            cp16(bBase + dstOff[i], Bm + (long long)(col0 + rowA[i]) * K + k0 + grpA[i] * 8);
        }
        asm volatile("cp.async.commit_group;");
    };

    issue(0, 0);
    for (int it = 0; it < nk; it++) {
        const int cur = it & 1;
        asm volatile("cp.async.wait_group 0;");
        __syncthreads();
        if (it + 1 < nk) issue((it + 1) * BK, cur ^ 1);

        const uint32_t aStage = sb + (uint32_t)cur * 32768u;
        const uint32_t bStage = aStage + 16384u;
        #pragma unroll
        for (int ks = 0; ks < 4; ks++) {             // k = ks*16
            const uint32_t kx = (uint32_t)ks << 5;   // 2 groups of 16B per kstep
            uint32_t afr[2][4], bfr[4][4];
            ldsm4(afr[0], (aStage + aRel[0]) ^ kx);
            ldsm4(afr[1], (aStage + aRel[1]) ^ kx);
            #pragma unroll
            for (int p = 0; p < 4; p++) ldsm4(bfr[p], (bStage + bRel[p]) ^ kx);
            #pragma unroll
            for (int mt = 0; mt < 2; mt++)
                #pragma unroll
                for (int nt = 0; nt < 8; nt++)
                    mma_f16(acc[mt * 8 + nt], afr[mt], &bfr[nt >> 1][(nt & 1) * 2]);
        }
        __syncthreads();
    }

    // ---------------- epilogue ----------------
    #pragma unroll
    for (int mt = 0; mt < 2; mt++) {
        #pragma unroll
        for (int nt = 0; nt < 8; nt++) {
            float* a4 = acc[mt * 8 + nt];
            int rb = row0 + wm * 32 + mt * 16 + g;
            int cb = col0 + wn * 64 + nt * 8 + tig * 2;
            #pragma unroll
            for (int half_i = 0; half_i < 2; half_i++) {
                int r = rb + half_i * 8;
                float v0 = a4[half_i * 2]     * alpha;
                float v1 = a4[half_i * 2 + 1] * alpha;
                if (bias) { v0 += bias[cb]; v1 += bias[cb + 1]; }
                if (flags & FLAG_RELU) { v0 = fmaxf(v0, 0.0f); v1 = fmaxf(v1, 0.0f); }
                if (flags & FLAG_CMASK) {
                    if (cb     > r) v0 = -1e30f;
                    if (cb + 1 > r) v1 = -1e30f;
                }
                if (flags & FLAG_OUTH) {
                    *(__half2*)(Ch + (long long)r * N + cb) = __floats2half2_rn(v0, v1);
                } else {
                    float2* p = (float2*)(C + (long long)r * N + cb);
                    if (flags & FLAG_ACCUM) {
                        float2 o = *p;
                        o.x += v0; o.y += v1;
                        *p = o;
                    } else {
                        *p = make_float2(v0, v1);
                    }
                }
            }
        }
    }
}

// ---------------- host orchestration ----------------
extern "C" void kernel_launch(void* const* d_in, const int* in_sizes, int n_in,
                              void* d_out, int out_size) {
    const float* q    = (const float*)d_in[0];
    const float* k    = (const float*)d_in[1];
    const float* v    = (const float*)d_in[2];
    const float* Wq_s = (const float*)d_in[3];
    const float* Wk_s = (const float*)d_in[4];
    const float* Wv_s = (const float*)d_in[5];
    const float* Wq_c = (const float*)d_in[6];
    const float* Wk_c = (const float*)d_in[7];
    const float* Wv_c = (const float*)d_in[8];
    const float* W1   = (const float*)d_in[9];
    const float* b1   = (const float*)d_in[10];
    const float* W2   = (const float*)d_in[11];
    const float* b2   = (const float*)d_in[12];
    const float* g1   = (const float*)d_in[13];
    const float* be1  = (const float*)d_in[14];
    const float* g2   = (const float*)d_in[15];
    const float* be2  = (const float*)d_in[16];
    const float* g3   = (const float*)d_in[17];
    const float* be3  = (const float*)d_in[18];
    float* out = (float*)d_out;

    __half *xn, *Qh, *Kh, *Vt, *P, *Wt, *kv;
    float  *S, *O;
    cudaGetSymbolAddress((void**)&xn, h_xn);
    cudaGetSymbolAddress((void**)&Qh, h_Qh);
    cudaGetSymbolAddress((void**)&Kh, h_Kh);
    cudaGetSymbolAddress((void**)&Vt, h_Vt);
    cudaGetSymbolAddress((void**)&P,  h_P);
    cudaGetSymbolAddress((void**)&Wt, h_Wt);
    cudaGetSymbolAddress((void**)&kv, h_kv);
    cudaGetSymbolAddress((void**)&S,  g_S);
    cudaGetSymbolAddress((void**)&O,  g_O);

    static bool attr_done = false;
    if (!attr_done) {
        cudaFuncSetAttribute(gemm_h, cudaFuncAttributeMaxDynamicSharedMemorySize, 65536);
        attr_done = true;
    }
    const int SMB = 65536;

    const long long sLE = (long long)L_ * E_;
    const long long sED = (long long)E_ * D_;
    const long long sLD = (long long)L_ * D_;
    const long long sLL = (long long)L_ * L_;
    const int BIG = 1 << 30;
    const float scl = 0.044194173824159216f;   // 512^-0.5
    const long long WSZ = (long long)H_ * E_ * D_;

    __half* Wqt = Wt;
    __half* Wkt = Wt + WSZ;
    __half* Wvt = Wt + 2 * WSZ;
    __half* W1t = Wt;             // reused in FFN phase
    __half* W2t = Wt + (long long)FE_ * E_;
    __half* kr  = kv;             // fp16 k
    __half* vr  = kv + sLE * B_;  // fp16 v

    const dim3 gQK(D_ / 128, L_ / 128, B_ * H_);   // (4,16,32)
    const dim3 gVt(L_ / 128, D_ / 128, B_ * H_);   // (16,4,32)
    const dim3 gSc(L_ / 128, L_ / 128, B_ * H_);   // (16,16,32)

    // ===== Block 1: pre-norm causal self-attention =====
    transpose_kernel<<<dim3(D_ / 32, E_ / 32, H_), 256>>>(Wq_s, Wqt, E_, D_);
    transpose_kernel<<<dim3(D_ / 32, E_ / 32, H_), 256>>>(Wk_s, Wkt, E_, D_);
    transpose_kernel<<<dim3(D_ / 32, E_ / 32, H_), 256>>>(Wv_s, Wvt, E_, D_);
    half_copy_kernel<<<(B_ * L_ * E_) / 1024, 256>>>(k, kr);
    half_copy_kernel<<<(B_ * L_ * E_) / 1024, 256>>>(v, vr);
    ln_kernel<<<B_ * L_, 256>>>(q, g1, be1, xn);
    // Qh[b,h] = xn[b] @ Wqt[h]^T
    gemm_h<<<gQK, 256, SMB>>>(xn, Wqt, Qh, L_, D_, E_, H_, B_, sLE, 1, H_, sED, sLD, nullptr, 1.f, FLAG_OUTH);
    gemm_h<<<gQK, 256, SMB>>>(xn, Wkt, Kh, L_, D_, E_, H_, B_, sLE, 1, H_, sED, sLD, nullptr, 1.f, FLAG_OUTH);
    // Vt[b,h] = Wvt[h] @ xn[b]^T  -> [D][L]
    gemm_h<<<gVt, 256, SMB>>>(Wvt, xn, Vt, D_, L_, E_, 1, H_, sED, H_, B_, sLE, sLD, nullptr, 1.f, FLAG_OUTH);
    // S = scl * Qh @ Kh^T (causal, fp32 out)
    gemm_h<<<gSc, 256, SMB>>>(Qh, Kh, S, L_, L_, D_, 1, BIG, sLD, 1, BIG, sLD, sLL, nullptr, scl, FLAG_CMASK);
    softmax_kernel<<<B_ * H_ * L_, 256>>>(S, P);
    // O = P @ Vt^T  (K capped at diag, fp32 out)
    gemm_h<<<gQK, 256, SMB>>>(P, Vt, O, L_, D_, L_, 1, BIG, sLL, 1, BIG, sLD, sLD, nullptr, 1.f, FLAG_CK);
    add_mean_kernel<<<(B_ * L_ * E_) / 256, 256>>>(q, O, out);    // out = q + mean_h(O)

    // ===== Block 2: pre-norm cross-attention (only queries normed) =====
    transpose_kernel<<<dim3(D_ / 32, E_ / 32, H_), 256>>>(Wq_c, Wqt, E_, D_);
    transpose_kernel<<<dim3(D_ / 32, E_ / 32, H_), 256>>>(Wk_c, Wkt, E_, D_);
    transpose_kernel<<<dim3(D_ / 32, E_ / 32, H_), 256>>>(Wv_c, Wvt, E_, D_);
    ln_kernel<<<B_ * L_, 256>>>(out, g2, be2, xn);
    gemm_h<<<gQK, 256, SMB>>>(xn, Wqt, Qh, L_, D_, E_, H_, B_, sLE, 1, H_, sED, sLD, nullptr, 1.f, FLAG_OUTH);
    gemm_h<<<gQK, 256, SMB>>>(kr, Wkt, Kh, L_, D_, E_, H_, B_, sLE, 1, H_, sED, sLD, nullptr, 1.f, FLAG_OUTH);
    gemm_h<<<gVt, 256, SMB>>>(Wvt, vr, Vt, D_, L_, E_, 1, H_, sED, H_, B_, sLE, sLD, nullptr, 1.f, FLAG_OUTH);
    gemm_h<<<gSc, 256, SMB>>>(Qh, Kh, S, L_, L_, D_, 1, BIG, sLD, 1, BIG, sLD, sLL, nullptr, scl, 0);
    softmax_kernel<<<B_ * H_ * L_, 256>>>(S, P);
    gemm_h<<<gQK, 256, SMB>>>(P, Vt, O, L_, D_, L_, 1, BIG, sLL, 1, BIG, sLD, sLD, nullptr, 1.f, 0);
    add_mean_kernel<<<(B_ * L_ * E_) / 256, 256>>>(out, O, out);  // out += mean_h(O)

    // ===== Block 3: FFN =====
    transpose_kernel<<<dim3(FE_ / 32, E_ / 32, 1), 256>>>(W1, W1t, E_, FE_);
    transpose_kernel<<<dim3(E_ / 32, FE_ / 32, 1), 256>>>(W2, W2t, FE_, E_);
    ln_kernel<<<B_ * L_, 256>>>(out, g3, be3, xn);
    // hidden = relu(xn @ W1t^T + b1) -> fp16, stored in P scratch: [B*L, 4E]
    gemm_h<<<dim3(FE_ / 128, (B_ * L_) / 128, 1), 256, SMB>>>(
        xn, W1t, P, B_ * L_, FE_, E_, 1, 1, 0, 1, 1, 0, 0, b1, 1.f, FLAG_RELU | FLAG_OUTH);
    // out += hidden @ W2t^T + b2
    gemm_h<<<dim3(E_ / 128, (B_ * L_) / 128, 1), 256, SMB>>>(
        P, W2t, out, B_ * L_, E_, FE_, 1, 1, 0, 1, 1, 0, 0, b2, 1.f, FLAG_ACCUM);
}

// round 8
// speedup vs baseline: 5.4370x; 1.0043x over previous
#include <cuda_runtime.h>
#include <cuda_fp16.h>
#include <math.h>
#include <stdint.h>

// Problem constants (fixed shapes from reference)
constexpr int B_ = 4, L_ = 2048, E_ = 512, H_ = 8, D_ = 512, FE_ = 2048; // FE = FW*E

#define FLAG_RELU    1
#define FLAG_ACCUM   2
#define FLAG_CMASK   4
#define FLAG_CK      8
#define FLAG_OUTH    16   // write output as fp16 (feeds a later GEMM)

// ---------------- static scratch (allocation-free) ----------------
__device__ __half h_xn[(size_t)B_ * L_ * E_];             //   8.4 MB LN output (fp16)
__device__ __half h_Qh[(size_t)B_ * H_ * L_ * D_];        //  67 MB per-head Q (fp16)
__device__ __half h_Kh[(size_t)B_ * H_ * L_ * D_];        //  67 MB per-head K (fp16)
__device__ __half h_Vt[(size_t)B_ * H_ * L_ * D_];        //  67 MB per-head V^T [D][L] (fp16)
__device__ float  g_S [(size_t)B_ * H_ * L_ * L_];        // 537 MB scores (fp32)
__device__ __half h_P [(size_t)B_ * H_ * L_ * L_];        // 268 MB probs (fp16, also FFN hidden)
__device__ float  g_O [(size_t)B_ * H_ * L_ * D_];        // 134 MB attn out (fp32)
__device__ __half h_Wt[(size_t)3 * H_ * E_ * D_];         //  12.6 MB transposed weights (fp16)
__device__ __half h_kv[(size_t)2 * B_ * L_ * E_];         //  16.8 MB fp16 k,v

// ---------------- block reductions (256 threads) ----------------
__device__ __forceinline__ float blk_sum(float v) {
    __shared__ float s[9];
    #pragma unroll
    for (int o = 16; o > 0; o >>= 1) v += __shfl_xor_sync(0xffffffffu, v, o);
    int w = threadIdx.x >> 5, lane = threadIdx.x & 31;
    __syncthreads();
    if (lane == 0) s[w] = v;
    __syncthreads();
    if (w == 0) {
        float t = (lane < 8) ? s[lane] : 0.0f;
        #pragma unroll
        for (int o = 4; o > 0; o >>= 1) t += __shfl_xor_sync(0xffffffffu, t, o);
        if (lane == 0) s[8] = t;
    }
    __syncthreads();
    return s[8];
}

__device__ __forceinline__ float blk_max(float v) {
    __shared__ float s[9];
    #pragma unroll
    for (int o = 16; o > 0; o >>= 1) v = fmaxf(v, __shfl_xor_sync(0xffffffffu, v, o));
    int w = threadIdx.x >> 5, lane = threadIdx.x & 31;
    __syncthreads();
    if (lane == 0) s[w] = v;
    __syncthreads();
    if (w == 0) {
        float t = (lane < 8) ? s[lane] : -3.4e38f;
        #pragma unroll
        for (int o = 4; o > 0; o >>= 1) t = fmaxf(t, __shfl_xor_sync(0xffffffffu, t, o));
        if (lane == 0) s[8] = t;
    }
    __syncthreads();
    return s[8];
}

// ---------------- LayerNorm (fp16 output: feeds GEMMs) ----------------
__global__ void ln_kernel(const float* __restrict__ x, const float* __restrict__ g,
                          const float* __restrict__ b, __half* __restrict__ y) {
    long long row = blockIdx.x;
    const float* xr = x + row * E_;
    __half*      yr = y + row * E_;
    int t = threadIdx.x;
    float a0 = xr[t], a1 = xr[t + 256];
    float mean = blk_sum(a0 + a1) * (1.0f / E_);
    float d0 = a0 - mean, d1 = a1 - mean;
    float var = blk_sum(d0 * d0 + d1 * d1) * (1.0f / E_);
    float inv = rsqrtf(var + 1e-5f);
    yr[t]       = __float2half_rn(d0 * inv * g[t]       + b[t]);
    yr[t + 256] = __float2half_rn(d1 * inv * g[t + 256] + b[t + 256]);
}

// ---------------- Softmax: fp32 scores in, fp16 probs out; causal-aware ----------
// causal: row l reads only cols [0, l], zero-fills (l, blockend) where
// blockend = ((l/128)+1)*128 (the region the K-capped AV GEMM will read).
__global__ void softmax_kernel(const float* __restrict__ S, __half* __restrict__ P,
                               int causal) {
    long long row = blockIdx.x;
    int l = (int)(row & (L_ - 1));                    // row index within the LxL matrix
    const float* r = S + row * (long long)L_;
    __half*      p = P + row * (long long)L_;
    int t = threadIdx.x;
    const int limit = causal ? (l + 1) : L_;
    const int zend  = causal ? min(((l >> 7) + 1) << 7, L_) : L_;

    float v[8];
    float mx = -3.4e38f;
    #pragma unroll
    for (int i = 0; i < 8; i++) {
        int idx = t + i * 256;
        v[i] = (idx < limit) ? r[idx] : -3.4e38f;
        mx = fmaxf(mx, v[i]);
    }
    mx = blk_max(mx);
    float s = 0.0f;
    #pragma unroll
    for (int i = 0; i < 8; i++) {
        int idx = t + i * 256;
        float e = (idx < limit) ? __expf(v[i] - mx) : 0.0f;
        v[i] = e;
        s += e;
    }
    s = blk_sum(s);
    float inv = 1.0f / s;
    #pragma unroll
    for (int i = 0; i < 8; i++) {
        int idx = t + i * 256;
        if (idx < limit)      p[idx] = __float2half_rn(v[i] * inv);
        else if (idx < zend)  p[idx] = __ushort_as_half((unsigned short)0);
    }
}

// ---------------- out[idx4] = base + mean_h Oh[b,h,.,.] (float4) ----------------
__global__ void add_mean_kernel(const float* __restrict__ base, const float* __restrict__ Oh,
                                float* __restrict__ out) {
    long long i4  = (long long)blockIdx.x * 256 + threadIdx.x;       // float4 index
    long long idx = i4 * 4;                                          // over B*L*E
    long long b   = idx >> 20;                                       // L*E = 2^20
    long long rem = idx & ((1LL << 20) - 1);
    const float* p = Oh + b * ((long long)H_ * L_ * D_) + rem;
    float4 s = make_float4(0.f, 0.f, 0.f, 0.f);
    #pragma unroll
    for (int h = 0; h < H_; h++) {
        float4 o = *(const float4*)(p + (long long)h * L_ * D_);
        s.x += o.x; s.y += o.y; s.z += o.z; s.w += o.w;
    }
    float4 bs = *(const float4*)(base + idx);
    s.x = bs.x + s.x * (1.0f / H_);
    s.y = bs.y + s.y * (1.0f / H_);
    s.z = bs.z + s.z * (1.0f / H_);
    s.w = bs.w + s.w * (1.0f / H_);
    *(float4*)(out + idx) = s;
}

// ---------------- elementwise fp16 copy (raw k,v -> fp16) ----------------
__global__ void half_copy_kernel(const float* __restrict__ X, __half* __restrict__ Y) {
    long long i = ((long long)blockIdx.x * 256 + threadIdx.x) * 4;
    float4 v = *(const float4*)(X + i);
    __half2* y = (__half2*)(Y + i);
    y[0] = __floats2half2_rn(v.x, v.y);
    y[1] = __floats2half2_rn(v.z, v.w);
}

// ---------------- Batched transpose (+fp16): Y[z][c][r] = h(X[z][r][c]) ----------
__global__ void transpose_kernel(const float* __restrict__ X, __half* __restrict__ Y,
                                 int R, int Cc) {
    __shared__ float t[32][33];
    long long zo = (long long)blockIdx.z * R * Cc;
    int c0 = blockIdx.x * 32, r0 = blockIdx.y * 32;
    int tx = threadIdx.x & 31, ty = threadIdx.x >> 5;   // 256 threads, ty=0..7
    #pragma unroll
    for (int i = 0; i < 32; i += 8)
        t[ty + i][tx] = X[zo + (long long)(r0 + ty + i) * Cc + c0 + tx];
    __syncthreads();
    #pragma unroll
    for (int i = 0; i < 32; i += 8)
        Y[zo + (long long)(c0 + ty + i) * R + r0 + tx] = __float2half_rn(t[tx][ty + i]);
}

// ---------------- mma / ldmatrix / cp.async helpers ----------------
__device__ __forceinline__ void mma_f16(float d[4], const uint32_t a[4], const uint32_t b[2]) {
    asm volatile(
        "mma.sync.aligned.m16n8k16.row.col.f32.f16.f16.f32 "
        "{%0,%1,%2,%3}, {%4,%5,%6,%7}, {%8,%9}, {%0,%1,%2,%3};"
        : "+f"(d[0]), "+f"(d[1]), "+f"(d[2]), "+f"(d[3])
        : "r"(a[0]), "r"(a[1]), "r"(a[2]), "r"(a[3]), "r"(b[0]), "r"(b[1]));
}

__device__ __forceinline__ void ldsm4(uint32_t r[4], uint32_t addr) {
    asm volatile("ldmatrix.sync.aligned.m8n8.x4.shared.b16 {%0,%1,%2,%3}, [%4];"
                 : "=r"(r[0]), "=r"(r[1]), "=r"(r[2]), "=r"(r[3]) : "r"(addr));
}

__device__ __forceinline__ void cp16(uint32_t dst, const void* src) {
    asm volatile("cp.async.cg.shared.global [%0], [%1], 16;" :: "r"(dst), "l"(src));
}

// ---------------- fp16 tensor-core GEMM (all-TRANSB, cp.async 2-stage) ----------
// C[z] = alpha * A[z] * B[z]^T (+bias)(relu)(+C)(causal); output fp32 or fp16.
// A: [M][K], B: [N][K] row-major fp16. BM=BN=128, BK=64 (row = 128B = 8 x 16B grp).
// 256 threads = 8 warps (4x2), warp tile 32x64, mma m16n8k16 f16.f32.
// SMEM (dynamic 64KB): stage s at s*32768: A tile 16KB then B tile 16KB.
// Swizzle: 16B group g of row r stored at byte r*128 + ((g ^ (r&7))<<4).
__global__ __launch_bounds__(256) void gemm_h(
    const __half* __restrict__ A, const __half* __restrict__ Bm, void* __restrict__ Cv,
    int M, int N, int K,
    int divA, int modA, long long sA, int divB, int modB, long long sB, long long sC,
    const float* __restrict__ bias, float alpha, int flags)
{
    constexpr int BM = 128, BK = 64;
    extern __shared__ uint32_t smem[];
    int z = blockIdx.z;
    A  += (long long)((z / divA) % modA) * sA;
    Bm += (long long)((z / divB) % modB) * sB;
    float*  C  = (float*)Cv + (long long)z * sC;
    __half* Ch = (__half*)Cv + (long long)z * sC;

    const int row0 = blockIdx.y * BM;
    const int col0 = blockIdx.x * 128;

    // Fully-masked causal block: nothing to do (softmax never reads this region).
    if ((flags & FLAG_CMASK) && col0 > row0 + BM - 1) return;

    const int tid  = threadIdx.x;
    const int lane = tid & 31, wid = tid >> 5;
    const int wm = wid & 3, wn = wid >> 2;          // warp at (wm*32, wn*64)
    const int g = lane >> 2, tig = lane & 3;        // mma groupID / thread-in-group
    const int r8 = lane & 7, q = lane >> 3;         // ldmatrix addressing

    const uint32_t sb = (uint32_t)__cvta_generic_to_shared(smem);

    // cp.async destinations: 1024 16B slots per operand tile; 4 per thread.
    uint32_t dstOff[4];
    int rowA[4], grpA[4];
    #pragma unroll
    for (int i = 0; i < 4; i++) {
        int s = tid + i * 256;
        int row = s >> 3, grp = s & 7;
        rowA[i] = row; grpA[i] = grp;
        dstOff[i] = (uint32_t)(row * 128 + ((grp ^ (row & 7)) << 4));
    }

    // ldmatrix relative base addresses (bytes within a stage's 16KB tile)
    uint32_t aRel[2], bRel[4];
    #pragma unroll
    for (int mt = 0; mt < 2; mt++) {
        int row = wm * 32 + mt * 16 + (q & 1) * 8 + r8;
        aRel[mt] = (uint32_t)(row * 128 + (((row & 7) ^ (q >> 1)) << 4));
    }
    #pragma unroll
    for (int p = 0; p < 4; p++) {
        int row = wn * 64 + p * 16 + (q >> 1) * 8 + r8;
        bRel[p] = (uint32_t)(row * 128 + (((row & 7) ^ (q & 1)) << 4));
    }

    float acc[16][4];
    #pragma unroll
    for (int i = 0; i < 16; i++)
        #pragma unroll
        for (int j = 0; j < 4; j++) acc[i][j] = 0.0f;

    int Kend = K;
    if (flags & FLAG_CK) Kend = min(K, row0 + BM);   // P cols beyond diag are exact 0
    const int nk = Kend / BK;

    auto issue = [&](int k0, int stg) {
        uint32_t aBase = sb + (uint32_t)stg * 32768u;
        uint32_t bBase = aBase + 16384u;
        #pragma unroll
        for (int i = 0; i < 4; i++) {
            cp16(aBase + dstOff[i], A  + (long long)(row0 + rowA[i]) * K + k0 + grpA[i] * 8);
            cp16(bBase + dstOff[i], Bm + (long long)(col0 + rowA[i]) * K + k0 + grpA[i] * 8);
        }
        asm volatile("cp.async.commit_group;");
    };

    issue(0, 0);
    for (int it = 0; it < nk; it++) {
        const int cur = it & 1;
        asm volatile("cp.async.wait_group 0;");
        __syncthreads();
        if (it + 1 < nk) issue((it + 1) * BK, cur ^ 1);

        const uint32_t aStage = sb + (uint32_t)cur * 32768u;
        const uint32_t bStage = aStage + 16384u;
        #pragma unroll
        for (int ks = 0; ks < 4; ks++) {             // k = ks*16
            const uint32_t kx = (uint32_t)ks << 5;   // 2 groups of 16B per kstep
            uint32_t afr[2][4], bfr[4][4];
            ldsm4(afr[0], (aStage + aRel[0]) ^ kx);
            ldsm4(afr[1], (aStage + aRel[1]) ^ kx);
            #pragma unroll
            for (int p = 0; p < 4; p++) ldsm4(bfr[p], (bStage + bRel[p]) ^ kx);
            #pragma unroll
            for (int mt = 0; mt < 2; mt++)
                #pragma unroll
                for (int nt = 0; nt < 8; nt++)
                    mma_f16(acc[mt * 8 + nt], afr[mt], &bfr[nt >> 1][(nt & 1) * 2]);
        }
        __syncthreads();
    }

    // ---------------- epilogue ----------------
    #pragma unroll
    for (int mt = 0; mt < 2; mt++) {
        #pragma unroll
        for (int nt = 0; nt < 8; nt++) {
            float* a4 = acc[mt * 8 + nt];
            int rb = row0 + wm * 32 + mt * 16 + g;
            int cb = col0 + wn * 64 + nt * 8 + tig * 2;
            #pragma unroll
            for (int half_i = 0; half_i < 2; half_i++) {
                int r = rb + half_i * 8;
                float v0 = a4[half_i * 2]     * alpha;
                float v1 = a4[half_i * 2 + 1] * alpha;
                if (bias) { v0 += bias[cb]; v1 += bias[cb + 1]; }
                if (flags & FLAG_RELU) { v0 = fmaxf(v0, 0.0f); v1 = fmaxf(v1, 0.0f); }
                if (flags & FLAG_CMASK) {
                    if (cb     > r) v0 = -1e30f;
                    if (cb + 1 > r) v1 = -1e30f;
                }
                if (flags & FLAG_OUTH) {
                    *(__half2*)(Ch + (long long)r * N + cb) = __floats2half2_rn(v0, v1);
                } else {
                    float2* p = (float2*)(C + (long long)r * N + cb);
                    if (flags & FLAG_ACCUM) {
                        float2 o = *p;
                        o.x += v0; o.y += v1;
                        *p = o;
                    } else {
                        *p = make_float2(v0, v1);
                    }
                }
            }
        }
    }
}

// ---------------- host orchestration ----------------
extern "C" void kernel_launch(void* const* d_in, const int* in_sizes, int n_in,
                              void* d_out, int out_size) {
    const float* q    = (const float*)d_in[0];
    const float* k    = (const float*)d_in[1];
    const float* v    = (const float*)d_in[2];
    const float* Wq_s = (const float*)d_in[3];
    const float* Wk_s = (const float*)d_in[4];
    const float* Wv_s = (const float*)d_in[5];
    const float* Wq_c = (const float*)d_in[6];
    const float* Wk_c = (const float*)d_in[7];
    const float* Wv_c = (const float*)d_in[8];
    const float* W1   = (const float*)d_in[9];
    const float* b1   = (const float*)d_in[10];
    const float* W2   = (const float*)d_in[11];
    const float* b2   = (const float*)d_in[12];
    const float* g1   = (const float*)d_in[13];
    const float* be1  = (const float*)d_in[14];
    const float* g2   = (const float*)d_in[15];
    const float* be2  = (const float*)d_in[16];
    const float* g3   = (const float*)d_in[17];
    const float* be3  = (const float*)d_in[18];
    float* out = (float*)d_out;

    __half *xn, *Qh, *Kh, *Vt, *P, *Wt, *kv;
    float  *S, *O;
    cudaGetSymbolAddress((void**)&xn, h_xn);
    cudaGetSymbolAddress((void**)&Qh, h_Qh);
    cudaGetSymbolAddress((void**)&Kh, h_Kh);
    cudaGetSymbolAddress((void**)&Vt, h_Vt);
    cudaGetSymbolAddress((void**)&P,  h_P);
    cudaGetSymbolAddress((void**)&Wt, h_Wt);
    cudaGetSymbolAddress((void**)&kv, h_kv);
    cudaGetSymbolAddress((void**)&S,  g_S);
    cudaGetSymbolAddress((void**)&O,  g_O);

    static bool attr_done = false;
    if (!attr_done) {
        cudaFuncSetAttribute(gemm_h, cudaFuncAttributeMaxDynamicSharedMemorySize, 65536);
        attr_done = true;
    }
    const int SMB = 65536;

    const long long sLE = (long long)L_ * E_;
    const long long sED = (long long)E_ * D_;
    const long long sLD = (long long)L_ * D_;
    const long long sLL = (long long)L_ * L_;
    const int BIG = 1 << 30;
    const float scl = 0.044194173824159216f;   // 512^-0.5
    const long long WSZ = (long long)H_ * E_ * D_;

    __half* Wqt = Wt;
    __half* Wkt = Wt + WSZ;
    __half* Wvt = Wt + 2 * WSZ;
    __half* W1t = Wt;             // reused in FFN phase
    __half* W2t = Wt + (long long)FE_ * E_;
    __half* kr  = kv;             // fp16 k
    __half* vr  = kv + sLE * B_;  // fp16 v

    const dim3 gQK(D_ / 128, L_ / 128, B_ * H_);   // (4,16,32)
    const dim3 gVt(L_ / 128, D_ / 128, B_ * H_);   // (16,4,32)
    const dim3 gSc(L_ / 128, L_ / 128, B_ * H_);   // (16,16,32)

    // ===== Block 1: pre-norm causal self-attention =====
    transpose_kernel<<<dim3(D_ / 32, E_ / 32, H_), 256>>>(Wq_s, Wqt, E_, D_);
    transpose_kernel<<<dim3(D_ / 32, E_ / 32, H_), 256>>>(Wk_s, Wkt, E_, D_);
    transpose_kernel<<<dim3(D_ / 32, E_ / 32, H_), 256>>>(Wv_s, Wvt, E_, D_);
    half_copy_kernel<<<(B_ * L_ * E_) / 1024, 256>>>(k, kr);
    half_copy_kernel<<<(B_ * L_ * E_) / 1024, 256>>>(v, vr);
    ln_kernel<<<B_ * L_, 256>>>(q, g1, be1, xn);
    // Qh[b,h] = xn[b] @ Wqt[h]^T
    gemm_h<<<gQK, 256, SMB>>>(xn, Wqt, Qh, L_, D_, E_, H_, B_, sLE, 1, H_, sED, sLD, nullptr, 1.f, FLAG_OUTH);
    gemm_h<<<gQK, 256, SMB>>>(xn, Wkt, Kh, L_, D_, E_, H_, B_, sLE, 1, H_, sED, sLD, nullptr, 1.f, FLAG_OUTH);
    // Vt[b,h] = Wvt[h] @ xn[b]^T  -> [D][L]
    gemm_h<<<gVt, 256, SMB>>>(Wvt, xn, Vt, D_, L_, E_, 1, H_, sED, H_, B_, sLE, sLD, nullptr, 1.f, FLAG_OUTH);
    // S = scl * Qh @ Kh^T (causal, fp32 out; masked blocks skipped entirely)
    gemm_h<<<gSc, 256, SMB>>>(Qh, Kh, S, L_, L_, D_, 1, BIG, sLD, 1, BIG, sLD, sLL, nullptr, scl, FLAG_CMASK);
    softmax_kernel<<<B_ * H_ * L_, 256>>>(S, P, 1);
    // O = P @ Vt^T  (K capped at diag, fp32 out)
    gemm_h<<<gQK, 256, SMB>>>(P, Vt, O, L_, D_, L_, 1, BIG, sLL, 1, BIG, sLD, sLD, nullptr, 1.f, FLAG_CK);
    add_mean_kernel<<<(B_ * L_ * E_) / 1024, 256>>>(q, O, out);    // out = q + mean_h(O)

    // ===== Block 2: pre-norm cross-attention (only queries normed) =====
    transpose_kernel<<<dim3(D_ / 32, E_ / 32, H_), 256>>>(Wq_c, Wqt, E_, D_);
    transpose_kernel<<<dim3(D_ / 32, E_ / 32, H_), 256>>>(Wk_c, Wkt, E_, D_);
    transpose_kernel<<<dim3(D_ / 32, E_ / 32, H_), 256>>>(Wv_c, Wvt, E_, D_);
    ln_kernel<<<B_ * L_, 256>>>(out, g2, be2, xn);
    gemm_h<<<gQK, 256, SMB>>>(xn, Wqt, Qh, L_, D_, E_, H_, B_, sLE, 1, H_, sED, sLD, nullptr, 1.f, FLAG_OUTH);
    gemm_h<<<gQK, 256, SMB>>>(kr, Wkt, Kh, L_, D_, E_, H_, B_, sLE, 1, H_, sED, sLD, nullptr, 1.f, FLAG_OUTH);
    gemm_h<<<gVt, 256, SMB>>>(Wvt, vr, Vt, D_, L_, E_, 1, H_, sED, H_, B_, sLE, sLD, nullptr, 1.f, FLAG_OUTH);
    gemm_h<<<gSc, 256, SMB>>>(Qh, Kh, S, L_, L_, D_, 1, BIG, sLD, 1, BIG, sLD, sLL, nullptr, scl, 0);
    softmax_kernel<<<B_ * H_ * L_, 256>>>(S, P, 0);
    gemm_h<<<gQK, 256, SMB>>>(P, Vt, O, L_, D_, L_, 1, BIG, sLL, 1, BIG, sLD, sLD, nullptr, 1.f, 0);
    add_mean_kernel<<<(B_ * L_ * E_) / 1024, 256>>>(out, O, out);  // out += mean_h(O)

    // ===== Block 3: FFN =====
    transpose_kernel<<<dim3(FE_ / 32, E_ / 32, 1), 256>>>(W1, W1t, E_, FE_);
    transpose_kernel<<<dim3(E_ / 32, FE_ / 32, 1), 256>>>(W2, W2t, FE_, E_);
    ln_kernel<<<B_ * L_, 256>>>(out, g3, be3, xn);
    // hidden = relu(xn @ W1t^T + b1) -> fp16, stored in P scratch: [B*L, 4E]
    gemm_h<<<dim3(FE_ / 128, (B_ * L_) / 128, 1), 256, SMB>>>(
        xn, W1t, P, B_ * L_, FE_, E_, 1, 1, 0, 1, 1, 0, 0, b1, 1.f, FLAG_RELU | FLAG_OUTH);
    // out += hidden @ W2t^T + b2
    gemm_h<<<dim3(E_ / 128, (B_ * L_) / 128, 1), 256, SMB>>>(
        P, W2t, out, B_ * L_, E_, FE_, 1, 1, 0, 1, 1, 0, 0, b2, 1.f, FLAG_ACCUM);
}

// round 9
// speedup vs baseline: 6.6410x; 1.2214x over previous
#include <cuda_runtime.h>
#include <cuda_fp16.h>
#include <math.h>
#include <stdint.h>

// Problem constants (fixed shapes from reference)
constexpr int B_ = 4, L_ = 2048, E_ = 512, H_ = 8, D_ = 512, FE_ = 2048; // FE = FW*E

#define FLAG_RELU    1
#define FLAG_ACCUM   2
#define FLAG_CMASK   4
#define FLAG_CK      8
#define FLAG_OUTH    16   // write output as fp16 (feeds a later GEMM / softmax)

// ---------------- static scratch (allocation-free) ----------------
__device__ __half h_xn[(size_t)B_ * L_ * E_];             //   8.4 MB LN output (fp16)
__device__ __half h_Qh[(size_t)B_ * H_ * L_ * D_];        //  67 MB per-head Q (fp16)
__device__ __half h_Kh[(size_t)B_ * H_ * L_ * D_];        //  67 MB per-head K (fp16)
__device__ __half h_Vt[(size_t)B_ * H_ * L_ * D_];        //  67 MB per-head V^T [D][L] (fp16)
__device__ __half h_S [(size_t)B_ * H_ * L_ * L_];        // 268 MB scores (fp16)
__device__ __half h_P [(size_t)B_ * H_ * L_ * L_];        // 268 MB probs (fp16, also FFN hidden)
__device__ float  g_O [(size_t)B_ * H_ * L_ * D_];        // 134 MB attn out (fp32)
__device__ __half h_Wt[(size_t)3 * H_ * E_ * D_];         //  12.6 MB transposed weights (fp16)
__device__ __half h_kv[(size_t)2 * B_ * L_ * E_];         //  16.8 MB fp16 k,v

// ---------------- block reductions (256 threads) ----------------
__device__ __forceinline__ float blk_sum(float v) {
    __shared__ float s[9];
    #pragma unroll
    for (int o = 16; o > 0; o >>= 1) v += __shfl_xor_sync(0xffffffffu, v, o);
    int w = threadIdx.x >> 5, lane = threadIdx.x & 31;
    __syncthreads();
    if (lane == 0) s[w] = v;
    __syncthreads();
    if (w == 0) {
        float t = (lane < 8) ? s[lane] : 0.0f;
        #pragma unroll
        for (int o = 4; o > 0; o >>= 1) t += __shfl_xor_sync(0xffffffffu, t, o);
        if (lane == 0) s[8] = t;
    }
    __syncthreads();
    return s[8];
}

__device__ __forceinline__ float blk_max(float v) {
    __shared__ float s[9];
    #pragma unroll
    for (int o = 16; o > 0; o >>= 1) v = fmaxf(v, __shfl_xor_sync(0xffffffffu, v, o));
    int w = threadIdx.x >> 5, lane = threadIdx.x & 31;
    __syncthreads();
    if (lane == 0) s[w] = v;
    __syncthreads();
    if (w == 0) {
        float t = (lane < 8) ? s[lane] : -3.4e38f;
        #pragma unroll
        for (int o = 4; o > 0; o >>= 1) t = fmaxf(t, __shfl_xor_sync(0xffffffffu, t, o));
        if (lane == 0) s[8] = t;
    }
    __syncthreads();
    return s[8];
}

// ---------------- LayerNorm (fp16 output: feeds GEMMs) ----------------
__global__ void ln_kernel(const float* __restrict__ x, const float* __restrict__ g,
                          const float* __restrict__ b, __half* __restrict__ y) {
    long long row = blockIdx.x;
    const float* xr = x + row * E_;
    __half*      yr = y + row * E_;
    int t = threadIdx.x;
    float a0 = xr[t], a1 = xr[t + 256];
    float mean = blk_sum(a0 + a1) * (1.0f / E_);
    float d0 = a0 - mean, d1 = a1 - mean;
    float var = blk_sum(d0 * d0 + d1 * d1) * (1.0f / E_);
    float inv = rsqrtf(var + 1e-5f);
    yr[t]       = __float2half_rn(d0 * inv * g[t]       + b[t]);
    yr[t + 256] = __float2half_rn(d1 * inv * g[t + 256] + b[t + 256]);
}

// ---------------- Softmax: fp16 scores in, fp16 probs out; causal-aware ----------
__global__ void softmax_kernel(const __half* __restrict__ S, __half* __restrict__ P,
                               int causal) {
    long long row = blockIdx.x;
    int l = (int)(row & (L_ - 1));                    // row index within the LxL matrix
    const __half* r = S + row * (long long)L_;
    __half*       p = P + row * (long long)L_;
    int t = threadIdx.x;
    const int limit = causal ? (l + 1) : L_;
    const int zend  = causal ? min(((l >> 7) + 1) << 7, L_) : L_;

    float v[8];
    float mx = -3.4e38f;
    #pragma unroll
    for (int i = 0; i < 8; i++) {
        int idx = t + i * 256;
        v[i] = (idx < limit) ? __half2float(r[idx]) : -3.4e38f;
        mx = fmaxf(mx, v[i]);
    }
    mx = blk_max(mx);
    float s = 0.0f;
    #pragma unroll
    for (int i = 0; i < 8; i++) {
        int idx = t + i * 256;
        float e = (idx < limit) ? __expf(v[i] - mx) : 0.0f;
        v[i] = e;
        s += e;
    }
    s = blk_sum(s);
    float inv = 1.0f / s;
    #pragma unroll
    for (int i = 0; i < 8; i++) {
        int idx = t + i * 256;
        if (idx < limit)      p[idx] = __float2half_rn(v[i] * inv);
        else if (idx < zend)  p[idx] = __ushort_as_half((unsigned short)0);
    }
}

// ---------------- out[idx4] = base + mean_h Oh[b,h,.,.] (float4) ----------------
__global__ void add_mean_kernel(const float* __restrict__ base, const float* __restrict__ Oh,
                                float* __restrict__ out) {
    long long i4  = (long long)blockIdx.x * 256 + threadIdx.x;       // float4 index
    long long idx = i4 * 4;                                          // over B*L*E
    long long b   = idx >> 20;                                       // L*E = 2^20
    long long rem = idx & ((1LL << 20) - 1);
    const float* p = Oh + b * ((long long)H_ * L_ * D_) + rem;
    float4 s = make_float4(0.f, 0.f, 0.f, 0.f);
    #pragma unroll
    for (int h = 0; h < H_; h++) {
        float4 o = *(const float4*)(p + (long long)h * L_ * D_);
        s.x += o.x; s.y += o.y; s.z += o.z; s.w += o.w;
    }
    float4 bs = *(const float4*)(base + idx);
    s.x = bs.x + s.x * (1.0f / H_);
    s.y = bs.y + s.y * (1.0f / H_);
    s.z = bs.z + s.z * (1.0f / H_);
    s.w = bs.w + s.w * (1.0f / H_);
    *(float4*)(out + idx) = s;
}

// ---------------- elementwise fp16 copy (raw k,v -> fp16) ----------------
__global__ void half_copy_kernel(const float* __restrict__ X, __half* __restrict__ Y) {
    long long i = ((long long)blockIdx.x * 256 + threadIdx.x) * 4;
    float4 v = *(const float4*)(X + i);
    __half2* y = (__half2*)(Y + i);
    y[0] = __floats2half2_rn(v.x, v.y);
    y[1] = __floats2half2_rn(v.z, v.w);
}

// ---------------- Batched transpose (+fp16): Y[z][c][r] = h(X[z][r][c]) ----------
__global__ void transpose_kernel(const float* __restrict__ X, __half* __restrict__ Y,
                                 int R, int Cc) {
    __shared__ float t[32][33];
    long long zo = (long long)blockIdx.z * R * Cc;
    int c0 = blockIdx.x * 32, r0 = blockIdx.y * 32;
    int tx = threadIdx.x & 31, ty = threadIdx.x >> 5;   // 256 threads, ty=0..7
    #pragma unroll
    for (int i = 0; i < 32; i += 8)
        t[ty + i][tx] = X[zo + (long long)(r0 + ty + i) * Cc + c0 + tx];
    __syncthreads();
    #pragma unroll
    for (int i = 0; i < 32; i += 8)
        Y[zo + (long long)(c0 + ty + i) * R + r0 + tx] = __float2half_rn(t[tx][ty + i]);
}

// ---------------- mma / ldmatrix / cp.async helpers ----------------
__device__ __forceinline__ void mma_f16(float d[4], const uint32_t a[4], const uint32_t b[2]) {
    asm volatile(
        "mma.sync.aligned.m16n8k16.row.col.f32.f16.f16.f32 "
        "{%0,%1,%2,%3}, {%4,%5,%6,%7}, {%8,%9}, {%0,%1,%2,%3};"
        : "+f"(d[0]), "+f"(d[1]), "+f"(d[2]), "+f"(d[3])
        : "r"(a[0]), "r"(a[1]), "r"(a[2]), "r"(a[3]), "r"(b[0]), "r"(b[1]));
}

__device__ __forceinline__ void ldsm4(uint32_t r[4], uint32_t addr) {
    asm volatile("ldmatrix.sync.aligned.m8n8.x4.shared.b16 {%0,%1,%2,%3}, [%4];"
                 : "=r"(r[0]), "=r"(r[1]), "=r"(r[2]), "=r"(r[3]) : "r"(addr));
}

__device__ __forceinline__ void cp16(uint32_t dst, const void* src) {
    asm volatile("cp.async.cg.shared.global [%0], [%1], 16;" :: "r"(dst), "l"(src));
}

// ---------------- fp16 tensor-core GEMM (all-TRANSB, cp.async 3-stage) ----------
// C[z] = alpha * A[z] * B[z]^T (+bias)(relu)(+C)(causal); output fp32 or fp16.
// A: [M][K], B: [N][K] row-major fp16. BM=BN=128, BK=64 (row = 128B = 8 x 16B grp).
// 256 threads = 8 warps (4x2), warp tile 32x64, mma m16n8k16 f16.f32.
// SMEM (dynamic 96KB): stage s at s*32768: A tile 16KB then B tile 16KB.
// Swizzle: 16B group g of row r stored at byte r*128 + ((g ^ (r&7))<<4).
// Pipeline: 2-chunk lookahead, wait_group 1, ONE __syncthreads per chunk
// (group count kept aligned with empty commit_group in tail iterations).
__global__ __launch_bounds__(256, 2) void gemm_h(
    const __half* __restrict__ A, const __half* __restrict__ Bm, void* __restrict__ Cv,
    int M, int N, int K,
    int divA, int modA, long long sA, int divB, int modB, long long sB, long long sC,
    const float* __restrict__ bias, float alpha, int flags)
{
    constexpr int BM = 128, BK = 64;
    extern __shared__ uint32_t smem[];
    int z = blockIdx.z;
    A  += (long long)((z / divA) % modA) * sA;
    Bm += (long long)((z / divB) % modB) * sB;
    float*  C  = (float*)Cv + (long long)z * sC;
    __half* Ch = (__half*)Cv + (long long)z * sC;

    const int row0 = blockIdx.y * BM;
    const int col0 = blockIdx.x * 128;

    // Fully-masked causal block: nothing to do (softmax never reads this region).
    if ((flags & FLAG_CMASK) && col0 > row0 + BM - 1) return;

    const int tid  = threadIdx.x;
    const int lane = tid & 31, wid = tid >> 5;
    const int wm = wid & 3, wn = wid >> 2;          // warp at (wm*32, wn*64)
    const int g = lane >> 2, tig = lane & 3;        // mma groupID / thread-in-group
    const int r8 = lane & 7, q = lane >> 3;         // ldmatrix addressing

    const uint32_t sb = (uint32_t)__cvta_generic_to_shared(smem);

    // cp.async destinations: 1024 16B slots per operand tile; 4 per thread.
    uint32_t dstOff[4];
    int rowA[4], grpA[4];
    #pragma unroll
    for (int i = 0; i < 4; i++) {
        int s = tid + i * 256;
        int row = s >> 3, grp = s & 7;
        rowA[i] = row; grpA[i] = grp;
        dstOff[i] = (uint32_t)(row * 128 + ((grp ^ (row & 7)) << 4));
    }

    // ldmatrix relative base addresses (bytes within a stage's 16KB tile)
    uint32_t aRel[2], bRel[4];
    #pragma unroll
    for (int mt = 0; mt < 2; mt++) {
        int row = wm * 32 + mt * 16 + (q & 1) * 8 + r8;
        aRel[mt] = (uint32_t)(row * 128 + (((row & 7) ^ (q >> 1)) << 4));
    }
    #pragma unroll
    for (int p = 0; p < 4; p++) {
        int row = wn * 64 + p * 16 + (q >> 1) * 8 + r8;
        bRel[p] = (uint32_t)(row * 128 + (((row & 7) ^ (q & 1)) << 4));
    }

    float acc[16][4];
    #pragma unroll
    for (int i = 0; i < 16; i++)
        #pragma unroll
        for (int j = 0; j < 4; j++) acc[i][j] = 0.0f;

    int Kend = K;
    if (flags & FLAG_CK) Kend = min(K, row0 + BM);   // P cols beyond diag are exact 0
    const int nk = Kend / BK;                        // >= 2 for every call here

    auto issue = [&](int chunk, int stg) {
        const int k0 = chunk * BK;
        uint32_t aBase = sb + (uint32_t)stg * 32768u;
        uint32_t bBase = aBase + 16384u;
        #pragma unroll
        for (int i = 0; i < 4; i++) {
            cp16(aBase + dstOff[i], A  + (long long)(row0 + rowA[i]) * K + k0 + grpA[i] * 8);
            cp16(bBase + dstOff[i], Bm + (long long)(col0 + rowA[i]) * K + k0 + grpA[i] * 8);
        }
        asm volatile("cp.async.commit_group;");
    };

    issue(0, 0);
    issue(1, 1);
    for (int it = 0; it < nk; it++) {
        asm volatile("cp.async.wait_group 1;");      // chunk `it` resident
        __syncthreads();                             // all warps done with stage (it+2)%3
        if (it + 2 < nk) issue(it + 2, (it + 2) % 3);
        else             asm volatile("cp.async.commit_group;");  // keep count aligned

        const uint32_t aStage = sb + (uint32_t)(it % 3) * 32768u;
        const uint32_t bStage = aStage + 16384u;
        #pragma unroll
        for (int ks = 0; ks < 4; ks++) {             // k = ks*16
            const uint32_t kx = (uint32_t)ks << 5;   // 2 groups of 16B per kstep
            uint32_t afr[2][4], bfr[4][4];
            ldsm4(afr[0], (aStage + aRel[0]) ^ kx);
            ldsm4(afr[1], (aStage + aRel[1]) ^ kx);
            #pragma unroll
            for (int p = 0; p < 4; p++) ldsm4(bfr[p], (bStage + bRel[p]) ^ kx);
            #pragma unroll
            for (int mt = 0; mt < 2; mt++)
                #pragma unroll
                for (int nt = 0; nt < 8; nt++)
                    mma_f16(acc[mt * 8 + nt], afr[mt], &bfr[nt >> 1][(nt & 1) * 2]);
        }
    }
    // NOTE: no trailing sync needed before epilogue — each thread only reads its acc.

    // ---------------- epilogue ----------------
    #pragma unroll
    for (int mt = 0; mt < 2; mt++) {
        #pragma unroll
        for (int nt = 0; nt < 8; nt++) {
            float* a4 = acc[mt * 8 + nt];
            int rb = row0 + wm * 32 + mt * 16 + g;
            int cb = col0 + wn * 64 + nt * 8 + tig * 2;
            #pragma unroll
            for (int half_i = 0; half_i < 2; half_i++) {
                int r = rb + half_i * 8;
                float v0 = a4[half_i * 2]     * alpha;
                float v1 = a4[half_i * 2 + 1] * alpha;
                if (bias) { v0 += bias[cb]; v1 += bias[cb + 1]; }
                if (flags & FLAG_RELU) { v0 = fmaxf(v0, 0.0f); v1 = fmaxf(v1, 0.0f); }
                if (flags & FLAG_CMASK) {
                    if (cb     > r) v0 = -60000.0f;   // fp16-representable "-inf"
                    if (cb + 1 > r) v1 = -60000.0f;
                }
                if (flags & FLAG_OUTH) {
                    *(__half2*)(Ch + (long long)r * N + cb) = __floats2half2_rn(v0, v1);
                } else {
                    float2* p = (float2*)(C + (long long)r * N + cb);
                    if (flags & FLAG_ACCUM) {
                        float2 o = *p;
                        o.x += v0; o.y += v1;
                        *p = o;
                    } else {
                        *p = make_float2(v0, v1);
                    }
                }
            }
        }
    }
}

// ---------------- host orchestration ----------------
extern "C" void kernel_launch(void* const* d_in, const int* in_sizes, int n_in,
                              void* d_out, int out_size) {
    const float* q    = (const float*)d_in[0];
    const float* k    = (const float*)d_in[1];
    const float* v    = (const float*)d_in[2];
    const float* Wq_s = (const float*)d_in[3];
    const float* Wk_s = (const float*)d_in[4];
    const float* Wv_s = (const float*)d_in[5];
    const float* Wq_c = (const float*)d_in[6];
    const float* Wk_c = (const float*)d_in[7];
    const float* Wv_c = (const float*)d_in[8];
    const float* W1   = (const float*)d_in[9];
    const float* b1   = (const float*)d_in[10];
    const float* W2   = (const float*)d_in[11];
    const float* b2   = (const float*)d_in[12];
    const float* g1   = (const float*)d_in[13];
    const float* be1  = (const float*)d_in[14];
    const float* g2   = (const float*)d_in[15];
    const float* be2  = (const float*)d_in[16];
    const float* g3   = (const float*)d_in[17];
    const float* be3  = (const float*)d_in[18];
    float* out = (float*)d_out;

    __half *xn, *Qh, *Kh, *Vt, *S, *P, *Wt, *kv;
    float  *O;
    cudaGetSymbolAddress((void**)&xn, h_xn);
    cudaGetSymbolAddress((void**)&Qh, h_Qh);
    cudaGetSymbolAddress((void**)&Kh, h_Kh);
    cudaGetSymbolAddress((void**)&Vt, h_Vt);
    cudaGetSymbolAddress((void**)&S,  h_S);
    cudaGetSymbolAddress((void**)&P,  h_P);
    cudaGetSymbolAddress((void**)&Wt, h_Wt);
    cudaGetSymbolAddress((void**)&kv, h_kv);
    cudaGetSymbolAddress((void**)&O,  g_O);

    static bool attr_done = false;
    if (!attr_done) {
        cudaFuncSetAttribute(gemm_h, cudaFuncAttributeMaxDynamicSharedMemorySize, 98304);
        attr_done = true;
    }
    const int SMB = 98304;   // 3 x 32KB stages

    const long long sLE = (long long)L_ * E_;
    const long long sED = (long long)E_ * D_;
    const long long sLD = (long long)L_ * D_;
    const long long sLL = (long long)L_ * L_;
    const int BIG = 1 << 30;
    const float scl = 0.044194173824159216f;   // 512^-0.5
    const long long WSZ = (long long)H_ * E_ * D_;

    __half* Wqt = Wt;
    __half* Wkt = Wt + WSZ;
    __half* Wvt = Wt + 2 * WSZ;
    __half* W1t = Wt;             // reused in FFN phase
    __half* W2t = Wt + (long long)FE_ * E_;
    __half* kr  = kv;             // fp16 k
    __half* vr  = kv + sLE * B_;  // fp16 v

    const dim3 gQK(D_ / 128, L_ / 128, B_ * H_);   // (4,16,32)
    const dim3 gVt(L_ / 128, D_ / 128, B_ * H_);   // (16,4,32)
    const dim3 gSc(L_ / 128, L_ / 128, B_ * H_);   // (16,16,32)

    // ===== Block 1: pre-norm causal self-attention =====
    transpose_kernel<<<dim3(D_ / 32, E_ / 32, H_), 256>>>(Wq_s, Wqt, E_, D_);
    transpose_kernel<<<dim3(D_ / 32, E_ / 32, H_), 256>>>(Wk_s, Wkt, E_, D_);
    transpose_kernel<<<dim3(D_ / 32, E_ / 32, H_), 256>>>(Wv_s, Wvt, E_, D_);
    half_copy_kernel<<<(B_ * L_ * E_) / 1024, 256>>>(k, kr);
    half_copy_kernel<<<(B_ * L_ * E_) / 1024, 256>>>(v, vr);
    ln_kernel<<<B_ * L_, 256>>>(q, g1, be1, xn);
    // Qh[b,h] = xn[b] @ Wqt[h]^T
    gemm_h<<<gQK, 256, SMB>>>(xn, Wqt, Qh, L_, D_, E_, H_, B_, sLE, 1, H_, sED, sLD, nullptr, 1.f, FLAG_OUTH);
    gemm_h<<<gQK, 256, SMB>>>(xn, Wkt, Kh, L_, D_, E_, H_, B_, sLE, 1, H_, sED, sLD, nullptr, 1.f, FLAG_OUTH);
    // Vt[b,h] = Wvt[h] @ xn[b]^T  -> [D][L]
    gemm_h<<<gVt, 256, SMB>>>(Wvt, xn, Vt, D_, L_, E_, 1, H_, sED, H_, B_, sLE, sLD, nullptr, 1.f, FLAG_OUTH);
    // S = scl * Qh @ Kh^T (causal, fp16 out; masked blocks skipped entirely)
    gemm_h<<<gSc, 256, SMB>>>(Qh, Kh, S, L_, L_, D_, 1, BIG, sLD, 1, BIG, sLD, sLL, nullptr, scl, FLAG_CMASK | FLAG_OUTH);
    softmax_kernel<<<B_ * H_ * L_, 256>>>(S, P, 1);
    // O = P @ Vt^T  (K capped at diag, fp32 out)
    gemm_h<<<gQK, 256, SMB>>>(P, Vt, O, L_, D_, L_, 1, BIG, sLL, 1, BIG, sLD, sLD, nullptr, 1.f, FLAG_CK);
    add_mean_kernel<<<(B_ * L_ * E_) / 1024, 256>>>(q, O, out);    // out = q + mean_h(O)

    // ===== Block 2: pre-norm cross-attention (only queries normed) =====
    transpose_kernel<<<dim3(D_ / 32, E_ / 32, H_), 256>>>(Wq_c, Wqt, E_, D_);
    transpose_kernel<<<dim3(D_ / 32, E_ / 32, H_), 256>>>(Wk_c, Wkt, E_, D_);
    transpose_kernel<<<dim3(D_ / 32, E_ / 32, H_), 256>>>(Wv_c, Wvt, E_, D_);
    ln_kernel<<<B_ * L_, 256>>>(out, g2, be2, xn);
    gemm_h<<<gQK, 256, SMB>>>(xn, Wqt, Qh, L_, D_, E_, H_, B_, sLE, 1, H_, sED, sLD, nullptr, 1.f, FLAG_OUTH);
    gemm_h<<<gQK, 256, SMB>>>(kr, Wkt, Kh, L_, D_, E_, H_, B_, sLE, 1, H_, sED, sLD, nullptr, 1.f, FLAG_OUTH);
    gemm_h<<<gVt, 256, SMB>>>(Wvt, vr, Vt, D_, L_, E_, 1, H_, sED, H_, B_, sLE, sLD, nullptr, 1.f, FLAG_OUTH);
    gemm_h<<<gSc, 256, SMB>>>(Qh, Kh, S, L_, L_, D_, 1, BIG, sLD, 1, BIG, sLD, sLL, nullptr, scl, FLAG_OUTH);
    softmax_kernel<<<B_ * H_ * L_, 256>>>(S, P, 0);
    gemm_h<<<gQK, 256, SMB>>>(P, Vt, O, L_, D_, L_, 1, BIG, sLL, 1, BIG, sLD, sLD, nullptr, 1.f, 0);
    add_mean_kernel<<<(B_ * L_ * E_) / 1024, 256>>>(out, O, out);  // out += mean_h(O)

    // ===== Block 3: FFN =====
    transpose_kernel<<<dim3(FE_ / 32, E_ / 32, 1), 256>>>(W1, W1t, E_, FE_);
    transpose_kernel<<<dim3(E_ / 32, FE_ / 32, 1), 256>>>(W2, W2t, FE_, E_);
    ln_kernel<<<B_ * L_, 256>>>(out, g3, be3, xn);
    // hidden = relu(xn @ W1t^T + b1) -> fp16, stored in P scratch: [B*L, 4E]
    gemm_h<<<dim3(FE_ / 128, (B_ * L_) / 128, 1), 256, SMB>>>(
        xn, W1t, P, B_ * L_, FE_, E_, 1, 1, 0, 1, 1, 0, 0, b1, 1.f, FLAG_RELU | FLAG_OUTH);
    // out += hidden @ W2t^T + b2
    gemm_h<<<dim3(E_ / 128, (B_ * L_) / 128, 1), 256, SMB>>>(
        P, W2t, out, B_ * L_, E_, FE_, 1, 1, 0, 1, 1, 0, 0, b2, 1.f, FLAG_ACCUM);
}